// round 12
// baseline (speedup 1.0000x reference)
#include <cuda_runtime.h>
#include <cuda_fp16.h>
#include <math.h>
#include <cstdint>

// ---------------- problem constants ----------------
#define T_TOK   2048
#define DM      4096
#define NH      32
#define KVH     8
#define HD      128
#define QKV_N   6144
#define CLIPV   8.0f
#define SCALE   0.08838834764831845f
#define KTOT    4096

// ---------------- scratch ----------------
__device__ __align__(16) __half g_ah  [T_TOK * DM];
__device__ __align__(16) __half g_bhi [QKV_N * DM];
__device__ __align__(16) __half g_blo [QKV_N * DM];
__device__ __align__(16) __half g_bohi[DM * DM];
__device__ __align__(16) __half g_qhi[T_TOK * DM];
__device__ __align__(16) __half g_qlo[T_TOK * DM];
__device__ __align__(16) __half g_khi[T_TOK * KVH * HD];
__device__ __align__(16) __half g_klo[T_TOK * KVH * HD];
__device__ __align__(16) __half g_vthi[KVH * HD * T_TOK];
__device__ __align__(16) __half g_vtlo[KVH * HD * T_TOK];

// heavy-first attention qb order (sorted by qb_local desc)
__device__ const int g_qb_order[32] = {
    19, 18, 17, 16, 15, 7, 14, 6, 13, 5, 25, 31, 12, 4, 24, 30,
    11, 3, 23, 29, 10, 2, 22, 28, 9, 1, 21, 27, 8, 0, 20, 26
};

// ============================ PTX helpers ============================
__device__ __forceinline__ uint32_t smem_u32_of(const void* p) {
    uint32_t a;
    asm("{ .reg .u64 t; cvta.to.shared.u64 t, %1; cvt.u32.u64 %0, t; }"
        : "=r"(a) : "l"(p));
    return a;
}
__device__ __forceinline__ void cp_async16(uint32_t dst, const void* src) {
    asm volatile("cp.async.cg.shared.global [%0], [%1], 16;" :: "r"(dst), "l"(src));
}
__device__ __forceinline__ void cp_commit() {
    asm volatile("cp.async.commit_group;" ::: "memory");
}
template<int N> __device__ __forceinline__ void cp_wait() {
    asm volatile("cp.async.wait_group %0;" :: "n"(N) : "memory");
}
__device__ __forceinline__ void ldsm4(uint32_t (&r)[4], uint32_t addr) {
    asm volatile("ldmatrix.sync.aligned.m8n8.x4.shared.b16 {%0,%1,%2,%3}, [%4];"
        : "=r"(r[0]), "=r"(r[1]), "=r"(r[2]), "=r"(r[3]) : "r"(addr));
}
__device__ __forceinline__ void mma16816(float (&d)[4], const uint32_t (&a)[4],
                                         const uint32_t* b) {
    asm volatile("mma.sync.aligned.m16n8k16.row.col.f32.f16.f16.f32 "
        "{%0,%1,%2,%3}, {%4,%5,%6,%7}, {%8,%9}, {%0,%1,%2,%3};"
        : "+f"(d[0]), "+f"(d[1]), "+f"(d[2]), "+f"(d[3])
        : "r"(a[0]), "r"(a[1]), "r"(a[2]), "r"(a[3]), "r"(b[0]), "r"(b[1]));
}
__device__ __forceinline__ uint32_t swoff(int row, int cch) {
    return (uint32_t)(row * 128 + (((cch) ^ (row & 7)) << 4));
}
__device__ __forceinline__ float clipf(float v) {
    return fminf(CLIPV, fmaxf(-CLIPV, v));
}

// ============================================================================
// convert fp32 -> fp16 (8 elems/thread)
// ============================================================================
__global__ void __launch_bounds__(256) cvt_half_kernel(
    const float* __restrict__ in, __half* __restrict__ out, int n8)
{
    int i = blockIdx.x * 256 + threadIdx.x;
    if (i >= n8) return;
    float4 v0 = ((const float4*)in)[2 * i];
    float4 v1 = ((const float4*)in)[2 * i + 1];
    float a[8] = {v0.x, v0.y, v0.z, v0.w, v1.x, v1.y, v1.z, v1.w};
    __half h[8];
#pragma unroll
    for (int j = 0; j < 8; j++) h[j] = __float2half(a[j]);
    ((uint4*)out)[i] = *(uint4*)h;
}

// ============================================================================
// split fp32 -> fp16 hi/lo (8 elems/thread)
// ============================================================================
__global__ void __launch_bounds__(256) split_kernel(
    const float* __restrict__ in, __half* __restrict__ hi,
    __half* __restrict__ lo, int n8)
{
    int i = blockIdx.x * 256 + threadIdx.x;
    if (i >= n8) return;
    float4 v0 = ((const float4*)in)[2 * i];
    float4 v1 = ((const float4*)in)[2 * i + 1];
    float a[8] = {v0.x, v0.y, v0.z, v0.w, v1.x, v1.y, v1.z, v1.w};
    __half h[8], l[8];
#pragma unroll
    for (int j = 0; j < 8; j++) {
        h[j] = __float2half(a[j]);
        l[j] = __float2half(a[j] - __half2float(h[j]));
    }
    ((uint4*)hi)[i] = *(uint4*)h;
    ((uint4*)lo)[i] = *(uint4*)l;
}

// ============================================================================
// HMMA GEMM, 2-pass B (R8 core; FUSED=1 adds QKV epilogue)
// ============================================================================
#define STAGE_BYTES 49152
#define GEMM_SMEM   (2 * STAGE_BYTES)
#define NCHUNK      (KTOT / 64)

template<int FUSED>
__global__ void __launch_bounds__(256, 2) gemm_tc_kernel(
    const __half* __restrict__ Ah, const __half* __restrict__ Bhi,
    const __half* __restrict__ Blo,
    float* __restrict__ C, int Ntot,
    const float* __restrict__ cs_, const float* __restrict__ sn_,
    __half* __restrict__ Qhi, __half* __restrict__ Qlo,
    __half* __restrict__ Khi, __half* __restrict__ Klo,
    __half* __restrict__ Vthi, __half* __restrict__ Vtlo)
{
    extern __shared__ char smem[];
    const uint32_t sb = smem_u32_of(smem);
    const int tid  = threadIdx.x;
    const int wid  = tid >> 5;
    const int lane = tid & 31;
    const int warp_m = wid >> 2;
    const int warp_n = wid & 3;
    const int m0 = blockIdx.y * 128;
    const int n0 = blockIdx.x * 128;

    const __half* srcs[3];
    srcs[0] = Ah; srcs[1] = Bhi; srcs[2] = Blo;

    const int g = lane >> 3, r = lane & 7;
    const int a_row  = warp_m * 64 + (g & 1) * 8 + r;
    const int a_csel = g >> 1;
    const int b_row  = warp_n * 32 + (g >> 1) * 8 + r;
    const int b_csel = g & 1;

    float acc[4][4][4];
#pragma unroll
    for (int i = 0; i < 4; i++)
#pragma unroll
        for (int j = 0; j < 4; j++)
#pragma unroll
            for (int k = 0; k < 4; k++) acc[i][j][k] = 0.0f;

#define LOAD_CHUNK(cc, ss) do { \
    const int k0_ = (cc) * 64; \
    const uint32_t sbase_ = sb + (ss) * STAGE_BYTES; \
    _Pragma("unroll") \
    for (int t_ = 0; t_ < 12; t_++) { \
        int id_ = tid + t_ * 256; \
        int tile_ = id_ >> 10; \
        int w_ = id_ & 1023; \
        int mrow_ = w_ >> 3; \
        int cch_ = w_ & 7; \
        int grow_ = (tile_ == 0) ? (m0 + mrow_) : (n0 + mrow_); \
        const void* src_ = srcs[tile_] + (size_t)grow_ * KTOT + k0_ + cch_ * 8; \
        uint32_t dst_ = sbase_ + tile_ * 16384 + mrow_ * 128 + ((cch_ ^ (mrow_ & 7)) << 4); \
        cp_async16(dst_, src_); \
    } \
    cp_commit(); \
} while (0)

    LOAD_CHUNK(0, 0);

    for (int c = 0; c < NCHUNK; c++) {
        __syncthreads();
        if (c + 1 < NCHUNK) {
            LOAD_CHUNK(c + 1, (c + 1) & 1);
            cp_wait<1>();
        } else {
            cp_wait<0>();
        }
        __syncthreads();

        const uint32_t st = sb + (c & 1) * STAGE_BYTES;
#pragma unroll
        for (int s = 0; s < 4; s++) {
            uint32_t a_f[4][4];
#pragma unroll
            for (int mi = 0; mi < 4; mi++) {
                int m = a_row + mi * 16;
                uint32_t off = (uint32_t)(m * 128) +
                               ((((s << 1) + a_csel) ^ (m & 7)) << 4);
                ldsm4(a_f[mi], st + off);
            }
            uint32_t b_hi[2][4], b_lo[2][4];
#pragma unroll
            for (int j = 0; j < 2; j++) {
                int n = b_row + j * 16;
                uint32_t off = (uint32_t)(n * 128) +
                               ((((s << 1) + b_csel) ^ (n & 7)) << 4);
                ldsm4(b_hi[j], st + 16384 + off);
                ldsm4(b_lo[j], st + 32768 + off);
            }
#pragma unroll
            for (int mi = 0; mi < 4; mi++) {
#pragma unroll
                for (int nj = 0; nj < 4; nj++) {
                    const uint32_t* bh = &b_hi[nj >> 1][(nj & 1) * 2];
                    const uint32_t* bl = &b_lo[nj >> 1][(nj & 1) * 2];
                    mma16816(acc[mi][nj], a_f[mi], bh);
                    mma16816(acc[mi][nj], a_f[mi], bl);
                }
            }
        }
    }

    const int qrow = lane >> 2;
    const int qcol = (lane & 3) * 2;

    if (!FUSED) {
#pragma unroll
        for (int mi = 0; mi < 4; mi++) {
#pragma unroll
            for (int nj = 0; nj < 4; nj++) {
                int m = m0 + warp_m * 64 + mi * 16 + qrow;
                int n = n0 + warp_n * 32 + nj * 8 + qcol;
                *(float2*)(C + (size_t)m * Ntot + n) =
                    make_float2(acc[mi][nj][0], acc[mi][nj][1]);
                *(float2*)(C + (size_t)(m + 8) * Ntot + n) =
                    make_float2(acc[mi][nj][2], acc[mi][nj][3]);
            }
        }
        return;
    }

    // ---- FUSED epilogue ----
    __syncthreads();
    float* Cs = (float*)smem;   // [128][132]
#pragma unroll
    for (int mi = 0; mi < 4; mi++) {
#pragma unroll
        for (int nj = 0; nj < 4; nj++) {
            int rr = warp_m * 64 + mi * 16 + qrow;
            int cc = warp_n * 32 + nj * 8 + qcol;
            Cs[rr * 132 + cc]           = clipf(acc[mi][nj][0]);
            Cs[rr * 132 + cc + 1]       = clipf(acc[mi][nj][1]);
            Cs[(rr + 8) * 132 + cc]     = clipf(acc[mi][nj][2]);
            Cs[(rr + 8) * 132 + cc + 1] = clipf(acc[mi][nj][3]);
        }
    }
    __syncthreads();

    const int head = n0 >> 7;
    if (head < NH + KVH) {
        __half *hi, *lo;
        size_t rowstride;
        int coff;
        if (head < NH) {
            hi = Qhi; lo = Qlo; rowstride = DM; coff = head * HD;
        } else {
            hi = Khi; lo = Klo; rowstride = KVH * HD; coff = (head - NH) * HD;
        }
        const int dp = (tid & 31) * 2;
        const int r0 = tid >> 5;
#pragma unroll
        for (int it = 0; it < 16; it++) {
            int row = it * 8 + r0;
            int tok = m0 + row;
            float c0 = cs_[tok * 64 + dp],     c1 = cs_[tok * 64 + dp + 1];
            float s0 = sn_[tok * 64 + dp],     s1 = sn_[tok * 64 + dp + 1];
            float x10 = Cs[row * 132 + dp],      x11 = Cs[row * 132 + dp + 1];
            float x20 = Cs[row * 132 + dp + 64], x21 = Cs[row * 132 + dp + 65];
            float y10 = x10 * c0 - x20 * s0, y11 = x11 * c1 - x21 * s1;
            float y20 = x20 * c0 + x10 * s0, y21 = x21 * c1 + x11 * s1;
            __half h10 = __float2half(y10), h11 = __float2half(y11);
            __half h20 = __float2half(y20), h21 = __float2half(y21);
            __half l10 = __float2half(y10 - __half2float(h10));
            __half l11 = __float2half(y11 - __half2float(h11));
            __half l20 = __float2half(y20 - __half2float(h20));
            __half l21 = __float2half(y21 - __half2float(h21));
            size_t ob = (size_t)tok * rowstride + coff;
            *(__half2*)(hi + ob + dp)      = __halves2half2(h10, h11);
            *(__half2*)(hi + ob + dp + 64) = __halves2half2(h20, h21);
            *(__half2*)(lo + ob + dp)      = __halves2half2(l10, l11);
            *(__half2*)(lo + ob + dp + 64) = __halves2half2(l20, l21);
        }
    } else {
        const int kvh = head - NH - KVH;
        const int d = tid & 127;
        const int hsel = tid >> 7;
        size_t obase = ((size_t)kvh * HD + d) * T_TOK + m0 + hsel * 64;
#pragma unroll
        for (int gb = 0; gb < 8; gb++) {
            __half hb[8], lb[8];
#pragma unroll
            for (int u = 0; u < 8; u++) {
                float v = Cs[(hsel * 64 + gb * 8 + u) * 132 + d];
                hb[u] = __float2half(v);
                lb[u] = __float2half(v - __half2float(hb[u]));
            }
            *(uint4*)(Vthi + obase + gb * 8) = *(uint4*)hb;
            *(uint4*)(Vtlo + obase + gb * 8) = *(uint4*)lb;
        }
    }
}

// ============================================================================
// HMMA GEMM, 1-pass fp16 B (O-projection). Stage: A 16KB | B 16KB; 2 stages.
// ============================================================================
#define STAGE1P_BYTES 32768
#define GEMM1P_SMEM   (2 * STAGE1P_BYTES)

__global__ void __launch_bounds__(256, 2) gemm1p_kernel(
    const __half* __restrict__ Ah, const __half* __restrict__ B,
    float* __restrict__ C, int Ntot)
{
    extern __shared__ char smem[];
    const uint32_t sb = smem_u32_of(smem);
    const int tid  = threadIdx.x;
    const int wid  = tid >> 5;
    const int lane = tid & 31;
    const int warp_m = wid >> 2;
    const int warp_n = wid & 3;
    const int m0 = blockIdx.y * 128;
    const int n0 = blockIdx.x * 128;

    const int g = lane >> 3, r = lane & 7;
    const int a_row  = warp_m * 64 + (g & 1) * 8 + r;
    const int a_csel = g >> 1;
    const int b_row  = warp_n * 32 + (g >> 1) * 8 + r;
    const int b_csel = g & 1;

    float acc[4][4][4];
#pragma unroll
    for (int i = 0; i < 4; i++)
#pragma unroll
        for (int j = 0; j < 4; j++)
#pragma unroll
            for (int k = 0; k < 4; k++) acc[i][j][k] = 0.0f;

#define LOAD_CHUNK1P(cc, ss) do { \
    const int k0_ = (cc) * 64; \
    const uint32_t sbase_ = sb + (ss) * STAGE1P_BYTES; \
    _Pragma("unroll") \
    for (int t_ = 0; t_ < 8; t_++) { \
        int id_ = tid + t_ * 256; \
        int tile_ = id_ >> 10; \
        int w_ = id_ & 1023; \
        int mrow_ = w_ >> 3; \
        int cch_ = w_ & 7; \
        const __half* base_ = tile_ ? B : Ah; \
        int grow_ = (tile_ == 0) ? (m0 + mrow_) : (n0 + mrow_); \
        uint32_t dst_ = sbase_ + tile_ * 16384 + mrow_ * 128 + ((cch_ ^ (mrow_ & 7)) << 4); \
        cp_async16(dst_, base_ + (size_t)grow_ * KTOT + k0_ + cch_ * 8); \
    } \
    cp_commit(); \
} while (0)

    LOAD_CHUNK1P(0, 0);

    for (int c = 0; c < NCHUNK; c++) {
        __syncthreads();
        if (c + 1 < NCHUNK) {
            LOAD_CHUNK1P(c + 1, (c + 1) & 1);
            cp_wait<1>();
        } else {
            cp_wait<0>();
        }
        __syncthreads();

        const uint32_t st = sb + (c & 1) * STAGE1P_BYTES;
#pragma unroll
        for (int s = 0; s < 4; s++) {
            uint32_t a_f[4][4];
#pragma unroll
            for (int mi = 0; mi < 4; mi++) {
                int m = a_row + mi * 16;
                uint32_t off = (uint32_t)(m * 128) +
                               ((((s << 1) + a_csel) ^ (m & 7)) << 4);
                ldsm4(a_f[mi], st + off);
            }
            uint32_t b_f[2][4];
#pragma unroll
            for (int j = 0; j < 2; j++) {
                int n = b_row + j * 16;
                uint32_t off = (uint32_t)(n * 128) +
                               ((((s << 1) + b_csel) ^ (n & 7)) << 4);
                ldsm4(b_f[j], st + 16384 + off);
            }
#pragma unroll
            for (int mi = 0; mi < 4; mi++) {
#pragma unroll
                for (int nj = 0; nj < 4; nj++) {
                    mma16816(acc[mi][nj], a_f[mi], &b_f[nj >> 1][(nj & 1) * 2]);
                }
            }
        }
    }

    const int qrow = lane >> 2;
    const int qcol = (lane & 3) * 2;
#pragma unroll
    for (int mi = 0; mi < 4; mi++) {
#pragma unroll
        for (int nj = 0; nj < 4; nj++) {
            int m = m0 + warp_m * 64 + mi * 16 + qrow;
            int n = n0 + warp_n * 32 + nj * 8 + qcol;
            *(float2*)(C + (size_t)m * Ntot + n) =
                make_float2(acc[mi][nj][0], acc[mi][nj][1]);
            *(float2*)(C + (size_t)(m + 8) * Ntot + n) =
                make_float2(acc[mi][nj][2], acc[mi][nj][3]);
        }
    }
}

// ============================================================================
// Tensor-core flash attention (R10/R11 proven), heavy-first qb order
// ============================================================================
#define ATT_QHI 0
#define ATT_QLO 16384
#define ATT_KHI 32768
#define ATT_KLO 65536
#define ATT_VHI 98304
#define ATT_VLO 131072
#define ATT_PS  163840
#define ATT_SS  172032
#define ATT_ALPHA (ATT_SS + 17408)
#define ATT_LROW  (ATT_ALPHA + 256)
#define ATT_SMEM  (ATT_LROW + 256)

__global__ void __launch_bounds__(256) attn_kernel(
    const __half* __restrict__ Qhi, const __half* __restrict__ Qlo,
    const __half* __restrict__ Khi, const __half* __restrict__ Klo,
    const __half* __restrict__ Vthi, const __half* __restrict__ Vtlo,
    __half* __restrict__ oh)
{
    extern __shared__ char smc[];
    const uint32_t sbm = smem_u32_of(smc);
    float* Ss     = (float*)(smc + ATT_SS);
    float* alphas = (float*)(smc + ATT_ALPHA);
    float* lrow   = (float*)(smc + ATT_LROW);

    const int tid = threadIdx.x;
    const int h   = blockIdx.y;
    const int qb  = g_qb_order[blockIdx.x];

    int seq, qb_local;
    if      (qb < 8)  { seq = 0; qb_local = qb; }
    else if (qb < 20) { seq = 1; qb_local = qb - 8; }
    else if (qb < 26) { seq = 2; qb_local = qb - 20; }
    else              { seq = 3; qb_local = qb - 26; }
    const int cu[4] = {0, 512, 1280, 1664};
    const int seq_start = cu[seq];
    const int q_start = seq_start + qb_local * 64;
    const int kh = h >> 2;

    const int wid = tid >> 5, lane = tid & 31;
    const int warp_m = wid & 3;
    const int warp_n = wid >> 2;
    const int g = lane >> 3, r = lane & 7;
    const int a_row  = warp_m * 16 + (g & 1) * 8 + r;
    const int a_csel = g >> 1;
    const int b_row  = warp_n * 32 + (g >> 1) * 8 + r;
    const int b_csel = g & 1;
    const int pb_row = (g >> 1) * 8 + r;
    const int qrow = lane >> 2, qcol = (lane & 3) * 2;
    const int srow = tid >> 2, sq = tid & 3;

#define LOAD_KV(tok0_, bb_) do { \
    _Pragma("unroll") \
    for (int t = 0; t < 8; t++) { \
        int id = tid + t * 256; \
        int buf = id >> 10; \
        int w = id & 1023; \
        int half_ = w >> 9; \
        int w2 = w & 511; \
        int trow = w2 >> 3, cch = w2 & 7; \
        const __half* src = (buf ? Klo : Khi) + \
            (size_t)((tok0_) + trow) * (KVH * HD) + kh * HD + half_ * 64 + cch * 8; \
        uint32_t dst = sbm + (buf ? ATT_KLO : ATT_KHI) + (bb_) * 16384 + \
                       half_ * 8192 + swoff(trow, cch); \
        cp_async16(dst, src); \
    } \
    _Pragma("unroll") \
    for (int t = 0; t < 8; t++) { \
        int id = tid + t * 256; \
        int buf = id >> 10; \
        int w = id & 1023; \
        int drow = w >> 3, cch = w & 7; \
        int half_ = drow >> 6, rl = drow & 63; \
        const __half* src = (buf ? Vtlo : Vthi) + \
            ((size_t)kh * HD + drow) * T_TOK + (tok0_) + cch * 8; \
        uint32_t dst = sbm + (buf ? ATT_VLO : ATT_VHI) + (bb_) * 16384 + \
                       half_ * 8192 + swoff(rl, cch); \
        cp_async16(dst, src); \
    } \
} while (0)

#pragma unroll
    for (int t = 0; t < 8; t++) {
        int id = tid + t * 256;
        int buf = id >> 10;
        int w = id & 1023;
        int half_ = w >> 9;
        int w2 = w & 511;
        int trow = w2 >> 3, cch = w2 & 7;
        const __half* src = (buf ? Qlo : Qhi) +
            (size_t)(q_start + trow) * DM + h * HD + half_ * 64 + cch * 8;
        uint32_t dst = sbm + (buf ? ATT_QLO : ATT_QHI) + half_ * 8192 + swoff(trow, cch);
        cp_async16(dst, src);
    }
    LOAD_KV(seq_start, 0);
    cp_commit();

    float m_run = -INFINITY, l_run = 0.0f;
    float o[8][4];
#pragma unroll
    for (int i = 0; i < 8; i++)
#pragma unroll
        for (int j = 0; j < 4; j++) o[i][j] = 0.0f;

    for (int kb = 0; kb <= qb_local; kb++) {
        const int cur = kb & 1;
        cp_wait<0>();
        __syncthreads();

        float sacc[4][4];
#pragma unroll
        for (int i = 0; i < 4; i++)
#pragma unroll
            for (int j = 0; j < 4; j++) sacc[i][j] = 0.0f;

#pragma unroll
        for (int half_ = 0; half_ < 2; half_++) {
#pragma unroll
            for (int s4 = 0; s4 < 4; s4++) {
                uint32_t offa = half_ * 8192 + swoff(a_row, (s4 << 1) + a_csel);
                uint32_t ah4[4], al4[4];
                ldsm4(ah4, sbm + ATT_QHI + offa);
                ldsm4(al4, sbm + ATT_QLO + offa);
                uint32_t bh[2][4], bl[2][4];
#pragma unroll
                for (int jb = 0; jb < 2; jb++) {
                    uint32_t offb = cur * 16384 + half_ * 8192 +
                                    swoff(b_row + jb * 16, (s4 << 1) + b_csel);
                    ldsm4(bh[jb], sbm + ATT_KHI + offb);
                    ldsm4(bl[jb], sbm + ATT_KLO + offb);
                }
#pragma unroll
                for (int nj = 0; nj < 4; nj++) {
                    const uint32_t* ph = &bh[nj >> 1][(nj & 1) * 2];
                    const uint32_t* pl = &bl[nj >> 1][(nj & 1) * 2];
                    mma16816(sacc[nj], ah4, ph);
                    mma16816(sacc[nj], ah4, pl);
                    mma16816(sacc[nj], al4, ph);
                }
            }
        }

        if (kb < qb_local) {
            LOAD_KV(seq_start + (kb + 1) * 64, cur ^ 1);
            cp_commit();
        }

        const bool diag = (kb == qb_local);
#pragma unroll
        for (int nj = 0; nj < 4; nj++) {
            int mloc = warp_m * 16 + qrow;
            int cloc = warp_n * 32 + nj * 8 + qcol;
            float v0 = sacc[nj][0] * SCALE;
            float v1 = sacc[nj][1] * SCALE;
            float v2 = sacc[nj][2] * SCALE;
            float v3 = sacc[nj][3] * SCALE;
            if (diag) {
                if (cloc     > mloc)     v0 = -1e30f;
                if (cloc + 1 > mloc)     v1 = -1e30f;
                if (cloc     > mloc + 8) v2 = -1e30f;
                if (cloc + 1 > mloc + 8) v3 = -1e30f;
            }
            Ss[mloc * 68 + cloc]           = v0;
            Ss[mloc * 68 + cloc + 1]       = v1;
            Ss[(mloc + 8) * 68 + cloc]     = v2;
            Ss[(mloc + 8) * 68 + cloc + 1] = v3;
        }
        __syncthreads();

        {
            float lmax = -INFINITY;
            int base = srow * 68 + sq * 16;
#pragma unroll
            for (int jj = 0; jj < 16; jj++)
                lmax = fmaxf(lmax, Ss[base + jj]);
            lmax = fmaxf(lmax, __shfl_xor_sync(0xffffffffu, lmax, 1));
            lmax = fmaxf(lmax, __shfl_xor_sync(0xffffffffu, lmax, 2));
            float m_new = fmaxf(m_run, lmax);
            float alpha = __expf(m_run - m_new);
            float lsum = 0.0f;
#pragma unroll
            for (int jj = 0; jj < 16; jj += 2) {
                float p0 = __expf(Ss[base + jj] - m_new);
                float p1 = __expf(Ss[base + jj + 1] - m_new);
                lsum += p0 + p1;
                int col = sq * 16 + jj;
                uint32_t byte = (uint32_t)(srow * 128) +
                    ((((col >> 3)) ^ (srow & 7)) << 4) + (col & 7) * 2;
                *(__half2*)(smc + ATT_PS + byte) = __floats2half2_rn(p0, p1);
            }
            lsum += __shfl_xor_sync(0xffffffffu, lsum, 1);
            lsum += __shfl_xor_sync(0xffffffffu, lsum, 2);
            l_run = l_run * alpha + lsum;
            m_run = m_new;
            if ((tid & 3) == 0) { alphas[srow] = alpha; lrow[srow] = l_run; }
        }
        __syncthreads();

        {
            float a0 = alphas[warp_m * 16 + qrow];
            float a1 = alphas[warp_m * 16 + qrow + 8];
#pragma unroll
            for (int nj = 0; nj < 8; nj++) {
                o[nj][0] *= a0; o[nj][1] *= a0;
                o[nj][2] *= a1; o[nj][3] *= a1;
            }
#pragma unroll
            for (int s4 = 0; s4 < 4; s4++) {
                uint32_t ap[4];
                ldsm4(ap, sbm + ATT_PS + swoff(a_row, (s4 << 1) + a_csel));
                uint32_t vh[4][4], vl[4][4];
#pragma unroll
                for (int nb = 0; nb < 4; nb++) {
                    uint32_t offv = cur * 16384 + warp_n * 8192 +
                        swoff(pb_row + nb * 16, (s4 << 1) + b_csel);
                    ldsm4(vh[nb], sbm + ATT_VHI + offv);
                    ldsm4(vl[nb], sbm + ATT_VLO + offv);
                }
#pragma unroll
                for (int nj = 0; nj < 8; nj++) {
                    const uint32_t* ph = &vh[nj >> 1][(nj & 1) * 2];
                    const uint32_t* pl = &vl[nj >> 1][(nj & 1) * 2];
                    mma16816(o[nj], ap, ph);
                    mma16816(o[nj], ap, pl);
                }
            }
        }
    }

    float inv0 = 1.0f / lrow[warp_m * 16 + qrow];
    float inv1 = 1.0f / lrow[warp_m * 16 + qrow + 8];
#pragma unroll
    for (int nj = 0; nj < 8; nj++) {
        int m = q_start + warp_m * 16 + qrow;
        int col = h * HD + warp_n * 64 + nj * 8 + qcol;
        *(__half2*)(oh + (size_t)m * DM + col) =
            __floats2half2_rn(o[nj][0] * inv0, o[nj][1] * inv0);
        *(__half2*)(oh + (size_t)(m + 8) * DM + col) =
            __floats2half2_rn(o[nj][2] * inv1, o[nj][3] * inv1);
    }
}

// ============================================================================
// launch
// ============================================================================
extern "C" void kernel_launch(void* const* d_in, const int* in_sizes, int n_in,
                              void* d_out, int out_size)
{
    const float* hs    = (const float*)d_in[0];
    const float* w_qkv = (const float*)d_in[1];
    const float* w_o   = (const float*)d_in[2];
    const float* cs    = (const float*)d_in[3];
    const float* sn    = (const float*)d_in[4];
    (void)in_sizes; (void)n_in;

    __half *ah, *bhi, *blo, *bohi, *qhi, *qlo, *khi, *klo, *vthi, *vtlo;
    cudaGetSymbolAddress((void**)&ah, g_ah);
    cudaGetSymbolAddress((void**)&bhi, g_bhi);
    cudaGetSymbolAddress((void**)&blo, g_blo);
    cudaGetSymbolAddress((void**)&bohi, g_bohi);
    cudaGetSymbolAddress((void**)&qhi, g_qhi);
    cudaGetSymbolAddress((void**)&qlo, g_qlo);
    cudaGetSymbolAddress((void**)&khi, g_khi);
    cudaGetSymbolAddress((void**)&klo, g_klo);
    cudaGetSymbolAddress((void**)&vthi, g_vthi);
    cudaGetSymbolAddress((void**)&vtlo, g_vtlo);

    static cudaStream_t s1 = nullptr, s2 = nullptr;
    static cudaEvent_t eFork = nullptr, eWqkv = nullptr, eWo = nullptr;
    static int init_done = 0;
    if (!init_done) {
        cudaFuncSetAttribute(attn_kernel, cudaFuncAttributeMaxDynamicSharedMemorySize,
                             ATT_SMEM);
        cudaFuncSetAttribute(gemm_tc_kernel<0>,
                             cudaFuncAttributeMaxDynamicSharedMemorySize, GEMM_SMEM);
        cudaFuncSetAttribute(gemm_tc_kernel<1>,
                             cudaFuncAttributeMaxDynamicSharedMemorySize, GEMM_SMEM);
        cudaFuncSetAttribute(gemm1p_kernel,
                             cudaFuncAttributeMaxDynamicSharedMemorySize, GEMM1P_SMEM);
        cudaStreamCreateWithFlags(&s1, cudaStreamNonBlocking);
        cudaStreamCreateWithFlags(&s2, cudaStreamNonBlocking);
        cudaEventCreateWithFlags(&eFork, cudaEventDisableTiming);
        cudaEventCreateWithFlags(&eWqkv, cudaEventDisableTiming);
        cudaEventCreateWithFlags(&eWo, cudaEventDisableTiming);
        init_done = 1;
    }

    cudaEventRecord(eFork, 0);
    cudaStreamWaitEvent(s1, eFork, 0);
    cudaStreamWaitEvent(s2, eFork, 0);

    split_kernel<<<(QKV_N * DM / 8) / 256, 256, 0, s1>>>(
        w_qkv, bhi, blo, QKV_N * DM / 8);
    cudaEventRecord(eWqkv, s1);

    // w_o: single fp16 (1-pass O-projection) — overlaps GEMM1
    cvt_half_kernel<<<(DM * DM / 8) / 256, 256, 0, s2>>>(w_o, bohi, DM * DM / 8);
    cudaEventRecord(eWo, s2);

    cvt_half_kernel<<<(T_TOK * DM / 8) / 256, 256>>>(hs, ah, T_TOK * DM / 8);
    cudaStreamWaitEvent(0, eWqkv, 0);

    // QKV projection with fused clip+RoPE+split / V-transpose epilogue
    gemm_tc_kernel<1><<<dim3(QKV_N / 128, T_TOK / 128), 256, GEMM_SMEM>>>(
        ah, bhi, blo, nullptr, QKV_N, cs, sn,
        qhi, qlo, khi, klo, vthi, vtlo);

    // tensor-core flash attention -> fp16 O into g_ah
    attn_kernel<<<dim3(32, NH), 256, ATT_SMEM>>>(qhi, qlo, khi, klo, vthi, vtlo, ah);

    // output projection (1-pass fp16)
    cudaStreamWaitEvent(0, eWo, 0);
    gemm1p_kernel<<<dim3(DM / 128, T_TOK / 128), 256, GEMM1P_SMEM>>>(
        ah, bohi, (float*)d_out, DM);
}

// round 13
// speedup vs baseline: 1.4969x; 1.4969x over previous
#include <cuda_runtime.h>
#include <cuda_fp16.h>
#include <math.h>
#include <cstdint>

// ---------------- problem constants ----------------
#define T_TOK   2048
#define DM      4096
#define NH      32
#define KVH     8
#define HD      128
#define QKV_N   6144
#define CLIPV   8.0f
#define SCALE   0.08838834764831845f
#define KTOT    4096

// ---------------- scratch ----------------
__device__ __align__(16) __half g_ah  [T_TOK * DM];
__device__ __align__(16) __half g_bhi [QKV_N * DM];
__device__ __align__(16) __half g_blo [QKV_N * DM];
__device__ __align__(16) __half g_bohi[DM * DM];
__device__ __align__(16) __half g_qhi[T_TOK * DM];
__device__ __align__(16) __half g_qlo[T_TOK * DM];
__device__ __align__(16) __half g_khi[T_TOK * KVH * HD];
__device__ __align__(16) __half g_klo[T_TOK * KVH * HD];
__device__ __align__(16) __half g_vthi[KVH * HD * T_TOK];
__device__ __align__(16) __half g_vtlo[KVH * HD * T_TOK];

// ============================ PTX helpers ============================
__device__ __forceinline__ uint32_t smem_u32_of(const void* p) {
    uint32_t a;
    asm("{ .reg .u64 t; cvta.to.shared.u64 t, %1; cvt.u32.u64 %0, t; }"
        : "=r"(a) : "l"(p));
    return a;
}
__device__ __forceinline__ void cp_async16(uint32_t dst, const void* src) {
    asm volatile("cp.async.cg.shared.global [%0], [%1], 16;" :: "r"(dst), "l"(src));
}
__device__ __forceinline__ void cp_commit() {
    asm volatile("cp.async.commit_group;" ::: "memory");
}
template<int N> __device__ __forceinline__ void cp_wait() {
    asm volatile("cp.async.wait_group %0;" :: "n"(N) : "memory");
}
__device__ __forceinline__ void ldsm4(uint32_t (&r)[4], uint32_t addr) {
    asm volatile("ldmatrix.sync.aligned.m8n8.x4.shared.b16 {%0,%1,%2,%3}, [%4];"
        : "=r"(r[0]), "=r"(r[1]), "=r"(r[2]), "=r"(r[3]) : "r"(addr));
}
__device__ __forceinline__ void mma16816(float (&d)[4], const uint32_t (&a)[4],
                                         const uint32_t* b) {
    asm volatile("mma.sync.aligned.m16n8k16.row.col.f32.f16.f16.f32 "
        "{%0,%1,%2,%3}, {%4,%5,%6,%7}, {%8,%9}, {%0,%1,%2,%3};"
        : "+f"(d[0]), "+f"(d[1]), "+f"(d[2]), "+f"(d[3])
        : "r"(a[0]), "r"(a[1]), "r"(a[2]), "r"(a[3]), "r"(b[0]), "r"(b[1]));
}
__device__ __forceinline__ uint32_t swoff(int row, int cch) {
    return (uint32_t)(row * 128 + (((cch) ^ (row & 7)) << 4));
}
__device__ __forceinline__ float clipf(float v) {
    return fminf(CLIPV, fmaxf(-CLIPV, v));
}

// ============================================================================
// convert fp32 -> fp16 (8 elems/thread)
// ============================================================================
__global__ void __launch_bounds__(256) cvt_half_kernel(
    const float* __restrict__ in, __half* __restrict__ out, int n8)
{
    int i = blockIdx.x * 256 + threadIdx.x;
    if (i >= n8) return;
    float4 v0 = ((const float4*)in)[2 * i];
    float4 v1 = ((const float4*)in)[2 * i + 1];
    float a[8] = {v0.x, v0.y, v0.z, v0.w, v1.x, v1.y, v1.z, v1.w};
    __half h[8];
#pragma unroll
    for (int j = 0; j < 8; j++) h[j] = __float2half(a[j]);
    ((uint4*)out)[i] = *(uint4*)h;
}

// ============================================================================
// split fp32 -> fp16 hi/lo (8 elems/thread)
// ============================================================================
__global__ void __launch_bounds__(256) split_kernel(
    const float* __restrict__ in, __half* __restrict__ hi,
    __half* __restrict__ lo, int n8)
{
    int i = blockIdx.x * 256 + threadIdx.x;
    if (i >= n8) return;
    float4 v0 = ((const float4*)in)[2 * i];
    float4 v1 = ((const float4*)in)[2 * i + 1];
    float a[8] = {v0.x, v0.y, v0.z, v0.w, v1.x, v1.y, v1.z, v1.w};
    __half h[8], l[8];
#pragma unroll
    for (int j = 0; j < 8; j++) {
        h[j] = __float2half(a[j]);
        l[j] = __float2half(a[j] - __half2float(h[j]));
    }
    ((uint4*)hi)[i] = *(uint4*)h;
    ((uint4*)lo)[i] = *(uint4*)l;
}

// ============================================================================
// HMMA GEMM, 2-pass B (R8 core; FUSED=1 adds QKV epilogue)
// ============================================================================
#define STAGE_BYTES 49152
#define GEMM_SMEM   (2 * STAGE_BYTES)
#define NCHUNK      (KTOT / 64)

template<int FUSED>
__global__ void __launch_bounds__(256, 2) gemm_tc_kernel(
    const __half* __restrict__ Ah, const __half* __restrict__ Bhi,
    const __half* __restrict__ Blo,
    float* __restrict__ C, int Ntot,
    const float* __restrict__ cs_, const float* __restrict__ sn_,
    __half* __restrict__ Qhi, __half* __restrict__ Qlo,
    __half* __restrict__ Khi, __half* __restrict__ Klo,
    __half* __restrict__ Vthi, __half* __restrict__ Vtlo)
{
    extern __shared__ char smem[];
    const uint32_t sb = smem_u32_of(smem);
    const int tid  = threadIdx.x;
    const int wid  = tid >> 5;
    const int lane = tid & 31;
    const int warp_m = wid >> 2;
    const int warp_n = wid & 3;
    const int m0 = blockIdx.y * 128;
    const int n0 = blockIdx.x * 128;

    const __half* srcs[3];
    srcs[0] = Ah; srcs[1] = Bhi; srcs[2] = Blo;

    const int g = lane >> 3, r = lane & 7;
    const int a_row  = warp_m * 64 + (g & 1) * 8 + r;
    const int a_csel = g >> 1;
    const int b_row  = warp_n * 32 + (g >> 1) * 8 + r;
    const int b_csel = g & 1;

    float acc[4][4][4];
#pragma unroll
    for (int i = 0; i < 4; i++)
#pragma unroll
        for (int j = 0; j < 4; j++)
#pragma unroll
            for (int k = 0; k < 4; k++) acc[i][j][k] = 0.0f;

#define LOAD_CHUNK(cc, ss) do { \
    const int k0_ = (cc) * 64; \
    const uint32_t sbase_ = sb + (ss) * STAGE_BYTES; \
    _Pragma("unroll") \
    for (int t_ = 0; t_ < 12; t_++) { \
        int id_ = tid + t_ * 256; \
        int tile_ = id_ >> 10; \
        int w_ = id_ & 1023; \
        int mrow_ = w_ >> 3; \
        int cch_ = w_ & 7; \
        int grow_ = (tile_ == 0) ? (m0 + mrow_) : (n0 + mrow_); \
        const void* src_ = srcs[tile_] + (size_t)grow_ * KTOT + k0_ + cch_ * 8; \
        uint32_t dst_ = sbase_ + tile_ * 16384 + mrow_ * 128 + ((cch_ ^ (mrow_ & 7)) << 4); \
        cp_async16(dst_, src_); \
    } \
    cp_commit(); \
} while (0)

    LOAD_CHUNK(0, 0);

    for (int c = 0; c < NCHUNK; c++) {
        __syncthreads();
        if (c + 1 < NCHUNK) {
            LOAD_CHUNK(c + 1, (c + 1) & 1);
            cp_wait<1>();
        } else {
            cp_wait<0>();
        }
        __syncthreads();

        const uint32_t st = sb + (c & 1) * STAGE_BYTES;
#pragma unroll
        for (int s = 0; s < 4; s++) {
            uint32_t a_f[4][4];
#pragma unroll
            for (int mi = 0; mi < 4; mi++) {
                int m = a_row + mi * 16;
                uint32_t off = (uint32_t)(m * 128) +
                               ((((s << 1) + a_csel) ^ (m & 7)) << 4);
                ldsm4(a_f[mi], st + off);
            }
            uint32_t b_hi[2][4], b_lo[2][4];
#pragma unroll
            for (int j = 0; j < 2; j++) {
                int n = b_row + j * 16;
                uint32_t off = (uint32_t)(n * 128) +
                               ((((s << 1) + b_csel) ^ (n & 7)) << 4);
                ldsm4(b_hi[j], st + 16384 + off);
                ldsm4(b_lo[j], st + 32768 + off);
            }
#pragma unroll
            for (int mi = 0; mi < 4; mi++) {
#pragma unroll
                for (int nj = 0; nj < 4; nj++) {
                    const uint32_t* bh = &b_hi[nj >> 1][(nj & 1) * 2];
                    const uint32_t* bl = &b_lo[nj >> 1][(nj & 1) * 2];
                    mma16816(acc[mi][nj], a_f[mi], bh);
                    mma16816(acc[mi][nj], a_f[mi], bl);
                }
            }
        }
    }

    const int qrow = lane >> 2;
    const int qcol = (lane & 3) * 2;

    if (!FUSED) {
#pragma unroll
        for (int mi = 0; mi < 4; mi++) {
#pragma unroll
            for (int nj = 0; nj < 4; nj++) {
                int m = m0 + warp_m * 64 + mi * 16 + qrow;
                int n = n0 + warp_n * 32 + nj * 8 + qcol;
                *(float2*)(C + (size_t)m * Ntot + n) =
                    make_float2(acc[mi][nj][0], acc[mi][nj][1]);
                *(float2*)(C + (size_t)(m + 8) * Ntot + n) =
                    make_float2(acc[mi][nj][2], acc[mi][nj][3]);
            }
        }
        return;
    }

    // ---- FUSED epilogue ----
    __syncthreads();
    float* Cs = (float*)smem;   // [128][132]
#pragma unroll
    for (int mi = 0; mi < 4; mi++) {
#pragma unroll
        for (int nj = 0; nj < 4; nj++) {
            int rr = warp_m * 64 + mi * 16 + qrow;
            int cc = warp_n * 32 + nj * 8 + qcol;
            Cs[rr * 132 + cc]           = clipf(acc[mi][nj][0]);
            Cs[rr * 132 + cc + 1]       = clipf(acc[mi][nj][1]);
            Cs[(rr + 8) * 132 + cc]     = clipf(acc[mi][nj][2]);
            Cs[(rr + 8) * 132 + cc + 1] = clipf(acc[mi][nj][3]);
        }
    }
    __syncthreads();

    const int head = n0 >> 7;
    if (head < NH + KVH) {
        __half *hi, *lo;
        size_t rowstride;
        int coff;
        if (head < NH) {
            hi = Qhi; lo = Qlo; rowstride = DM; coff = head * HD;
        } else {
            hi = Khi; lo = Klo; rowstride = KVH * HD; coff = (head - NH) * HD;
        }
        const int dp = (tid & 31) * 2;
        const int r0 = tid >> 5;
#pragma unroll
        for (int it = 0; it < 16; it++) {
            int row = it * 8 + r0;
            int tok = m0 + row;
            float c0 = cs_[tok * 64 + dp],     c1 = cs_[tok * 64 + dp + 1];
            float s0 = sn_[tok * 64 + dp],     s1 = sn_[tok * 64 + dp + 1];
            float x10 = Cs[row * 132 + dp],      x11 = Cs[row * 132 + dp + 1];
            float x20 = Cs[row * 132 + dp + 64], x21 = Cs[row * 132 + dp + 65];
            float y10 = x10 * c0 - x20 * s0, y11 = x11 * c1 - x21 * s1;
            float y20 = x20 * c0 + x10 * s0, y21 = x21 * c1 + x11 * s1;
            __half h10 = __float2half(y10), h11 = __float2half(y11);
            __half h20 = __float2half(y20), h21 = __float2half(y21);
            __half l10 = __float2half(y10 - __half2float(h10));
            __half l11 = __float2half(y11 - __half2float(h11));
            __half l20 = __float2half(y20 - __half2float(h20));
            __half l21 = __float2half(y21 - __half2float(h21));
            size_t ob = (size_t)tok * rowstride + coff;
            *(__half2*)(hi + ob + dp)      = __halves2half2(h10, h11);
            *(__half2*)(hi + ob + dp + 64) = __halves2half2(h20, h21);
            *(__half2*)(lo + ob + dp)      = __halves2half2(l10, l11);
            *(__half2*)(lo + ob + dp + 64) = __halves2half2(l20, l21);
        }
    } else {
        const int kvh = head - NH - KVH;
        const int d = tid & 127;
        const int hsel = tid >> 7;
        size_t obase = ((size_t)kvh * HD + d) * T_TOK + m0 + hsel * 64;
#pragma unroll
        for (int gb = 0; gb < 8; gb++) {
            __half hb[8], lb[8];
#pragma unroll
            for (int u = 0; u < 8; u++) {
                float v = Cs[(hsel * 64 + gb * 8 + u) * 132 + d];
                hb[u] = __float2half(v);
                lb[u] = __float2half(v - __half2float(hb[u]));
            }
            *(uint4*)(Vthi + obase + gb * 8) = *(uint4*)hb;
            *(uint4*)(Vtlo + obase + gb * 8) = *(uint4*)lb;
        }
    }
}

// ============================================================================
// HMMA GEMM, 1-pass fp16 B (O-projection). Stage: A 16KB | B 16KB; 3 stages.
// ============================================================================
#define STAGE1P_BYTES 32768
#define GEMM1P_SMEM   (3 * STAGE1P_BYTES)

__global__ void __launch_bounds__(256, 2) gemm1p_kernel(
    const __half* __restrict__ Ah, const __half* __restrict__ B,
    float* __restrict__ C, int Ntot)
{
    extern __shared__ char smem[];
    const uint32_t sb = smem_u32_of(smem);
    const int tid  = threadIdx.x;
    const int wid  = tid >> 5;
    const int lane = tid & 31;
    const int warp_m = wid >> 2;
    const int warp_n = wid & 3;
    const int m0 = blockIdx.y * 128;
    const int n0 = blockIdx.x * 128;

    const int g = lane >> 3, r = lane & 7;
    const int a_row  = warp_m * 64 + (g & 1) * 8 + r;
    const int a_csel = g >> 1;
    const int b_row  = warp_n * 32 + (g >> 1) * 8 + r;
    const int b_csel = g & 1;

    float acc[4][4][4];
#pragma unroll
    for (int i = 0; i < 4; i++)
#pragma unroll
        for (int j = 0; j < 4; j++)
#pragma unroll
            for (int k = 0; k < 4; k++) acc[i][j][k] = 0.0f;

#define LOAD_CHUNK1P(cc, ss) do { \
    const int k0_ = (cc) * 64; \
    const uint32_t sbase_ = sb + (ss) * STAGE1P_BYTES; \
    _Pragma("unroll") \
    for (int t_ = 0; t_ < 8; t_++) { \
        int id_ = tid + t_ * 256; \
        int tile_ = id_ >> 10; \
        int w_ = id_ & 1023; \
        int mrow_ = w_ >> 3; \
        int cch_ = w_ & 7; \
        const __half* base_ = tile_ ? B : Ah; \
        int grow_ = (tile_ == 0) ? (m0 + mrow_) : (n0 + mrow_); \
        uint32_t dst_ = sbase_ + tile_ * 16384 + mrow_ * 128 + ((cch_ ^ (mrow_ & 7)) << 4); \
        cp_async16(dst_, base_ + (size_t)grow_ * KTOT + k0_ + cch_ * 8); \
    } \
    cp_commit(); \
} while (0)

    LOAD_CHUNK1P(0, 0);
    LOAD_CHUNK1P(1, 1);

    int stage = 0, lstage = 2;
    for (int c = 0; c < NCHUNK; c++) {
        if (c == NCHUNK - 1) cp_wait<0>(); else cp_wait<1>();
        __syncthreads();

        if (c + 2 < NCHUNK) LOAD_CHUNK1P(c + 2, lstage);

        const uint32_t st = sb + stage * STAGE1P_BYTES;
#pragma unroll
        for (int s = 0; s < 4; s++) {
            uint32_t a_f[4][4];
#pragma unroll
            for (int mi = 0; mi < 4; mi++) {
                int m = a_row + mi * 16;
                uint32_t off = (uint32_t)(m * 128) +
                               ((((s << 1) + a_csel) ^ (m & 7)) << 4);
                ldsm4(a_f[mi], st + off);
            }
            uint32_t b_f[2][4];
#pragma unroll
            for (int j = 0; j < 2; j++) {
                int n = b_row + j * 16;
                uint32_t off = (uint32_t)(n * 128) +
                               ((((s << 1) + b_csel) ^ (n & 7)) << 4);
                ldsm4(b_f[j], st + 16384 + off);
            }
#pragma unroll
            for (int mi = 0; mi < 4; mi++) {
#pragma unroll
                for (int nj = 0; nj < 4; nj++) {
                    mma16816(acc[mi][nj], a_f[mi], &b_f[nj >> 1][(nj & 1) * 2]);
                }
            }
        }
        stage = (stage == 2) ? 0 : stage + 1;
        lstage = (lstage == 2) ? 0 : lstage + 1;
    }

    const int qrow = lane >> 2;
    const int qcol = (lane & 3) * 2;
#pragma unroll
    for (int mi = 0; mi < 4; mi++) {
#pragma unroll
        for (int nj = 0; nj < 4; nj++) {
            int m = m0 + warp_m * 64 + mi * 16 + qrow;
            int n = n0 + warp_n * 32 + nj * 8 + qcol;
            *(float2*)(C + (size_t)m * Ntot + n) =
                make_float2(acc[mi][nj][0], acc[mi][nj][1]);
            *(float2*)(C + (size_t)(m + 8) * Ntot + n) =
                make_float2(acc[mi][nj][2], acc[mi][nj][3]);
        }
    }
}

// ============================================================================
// Tensor-core flash attention (R10/R11 proven, natural qb order)
// ============================================================================
#define ATT_QHI 0
#define ATT_QLO 16384
#define ATT_KHI 32768
#define ATT_KLO 65536
#define ATT_VHI 98304
#define ATT_VLO 131072
#define ATT_PS  163840
#define ATT_SS  172032
#define ATT_ALPHA (ATT_SS + 17408)
#define ATT_LROW  (ATT_ALPHA + 256)
#define ATT_SMEM  (ATT_LROW + 256)

__global__ void __launch_bounds__(256) attn_kernel(
    const __half* __restrict__ Qhi, const __half* __restrict__ Qlo,
    const __half* __restrict__ Khi, const __half* __restrict__ Klo,
    const __half* __restrict__ Vthi, const __half* __restrict__ Vtlo,
    __half* __restrict__ oh)
{
    extern __shared__ char smc[];
    const uint32_t sbm = smem_u32_of(smc);
    float* Ss     = (float*)(smc + ATT_SS);
    float* alphas = (float*)(smc + ATT_ALPHA);
    float* lrow   = (float*)(smc + ATT_LROW);

    const int tid = threadIdx.x;
    const int h   = blockIdx.y;
    const int qb  = blockIdx.x;

    int seq, qb_local;
    if      (qb < 8)  { seq = 0; qb_local = qb; }
    else if (qb < 20) { seq = 1; qb_local = qb - 8; }
    else if (qb < 26) { seq = 2; qb_local = qb - 20; }
    else              { seq = 3; qb_local = qb - 26; }
    const int cu[4] = {0, 512, 1280, 1664};
    const int seq_start = cu[seq];
    const int q_start = seq_start + qb_local * 64;
    const int kh = h >> 2;

    const int wid = tid >> 5, lane = tid & 31;
    const int warp_m = wid & 3;
    const int warp_n = wid >> 2;
    const int g = lane >> 3, r = lane & 7;
    const int a_row  = warp_m * 16 + (g & 1) * 8 + r;
    const int a_csel = g >> 1;
    const int b_row  = warp_n * 32 + (g >> 1) * 8 + r;
    const int b_csel = g & 1;
    const int pb_row = (g >> 1) * 8 + r;
    const int qrow = lane >> 2, qcol = (lane & 3) * 2;
    const int srow = tid >> 2, sq = tid & 3;

#define LOAD_KV(tok0_, bb_) do { \
    _Pragma("unroll") \
    for (int t = 0; t < 8; t++) { \
        int id = tid + t * 256; \
        int buf = id >> 10; \
        int w = id & 1023; \
        int half_ = w >> 9; \
        int w2 = w & 511; \
        int trow = w2 >> 3, cch = w2 & 7; \
        const __half* src = (buf ? Klo : Khi) + \
            (size_t)((tok0_) + trow) * (KVH * HD) + kh * HD + half_ * 64 + cch * 8; \
        uint32_t dst = sbm + (buf ? ATT_KLO : ATT_KHI) + (bb_) * 16384 + \
                       half_ * 8192 + swoff(trow, cch); \
        cp_async16(dst, src); \
    } \
    _Pragma("unroll") \
    for (int t = 0; t < 8; t++) { \
        int id = tid + t * 256; \
        int buf = id >> 10; \
        int w = id & 1023; \
        int drow = w >> 3, cch = w & 7; \
        int half_ = drow >> 6, rl = drow & 63; \
        const __half* src = (buf ? Vtlo : Vthi) + \
            ((size_t)kh * HD + drow) * T_TOK + (tok0_) + cch * 8; \
        uint32_t dst = sbm + (buf ? ATT_VLO : ATT_VHI) + (bb_) * 16384 + \
                       half_ * 8192 + swoff(rl, cch); \
        cp_async16(dst, src); \
    } \
} while (0)

#pragma unroll
    for (int t = 0; t < 8; t++) {
        int id = tid + t * 256;
        int buf = id >> 10;
        int w = id & 1023;
        int half_ = w >> 9;
        int w2 = w & 511;
        int trow = w2 >> 3, cch = w2 & 7;
        const __half* src = (buf ? Qlo : Qhi) +
            (size_t)(q_start + trow) * DM + h * HD + half_ * 64 + cch * 8;
        uint32_t dst = sbm + (buf ? ATT_QLO : ATT_QHI) + half_ * 8192 + swoff(trow, cch);
        cp_async16(dst, src);
    }
    LOAD_KV(seq_start, 0);
    cp_commit();

    float m_run = -INFINITY, l_run = 0.0f;
    float o[8][4];
#pragma unroll
    for (int i = 0; i < 8; i++)
#pragma unroll
        for (int j = 0; j < 4; j++) o[i][j] = 0.0f;

    for (int kb = 0; kb <= qb_local; kb++) {
        const int cur = kb & 1;
        cp_wait<0>();
        __syncthreads();

        float sacc[4][4];
#pragma unroll
        for (int i = 0; i < 4; i++)
#pragma unroll
            for (int j = 0; j < 4; j++) sacc[i][j] = 0.0f;

#pragma unroll
        for (int half_ = 0; half_ < 2; half_++) {
#pragma unroll
            for (int s4 = 0; s4 < 4; s4++) {
                uint32_t offa = half_ * 8192 + swoff(a_row, (s4 << 1) + a_csel);
                uint32_t ah4[4], al4[4];
                ldsm4(ah4, sbm + ATT_QHI + offa);
                ldsm4(al4, sbm + ATT_QLO + offa);
                uint32_t bh[2][4], bl[2][4];
#pragma unroll
                for (int jb = 0; jb < 2; jb++) {
                    uint32_t offb = cur * 16384 + half_ * 8192 +
                                    swoff(b_row + jb * 16, (s4 << 1) + b_csel);
                    ldsm4(bh[jb], sbm + ATT_KHI + offb);
                    ldsm4(bl[jb], sbm + ATT_KLO + offb);
                }
#pragma unroll
                for (int nj = 0; nj < 4; nj++) {
                    const uint32_t* ph = &bh[nj >> 1][(nj & 1) * 2];
                    const uint32_t* pl = &bl[nj >> 1][(nj & 1) * 2];
                    mma16816(sacc[nj], ah4, ph);
                    mma16816(sacc[nj], ah4, pl);
                    mma16816(sacc[nj], al4, ph);
                }
            }
        }

        if (kb < qb_local) {
            LOAD_KV(seq_start + (kb + 1) * 64, cur ^ 1);
            cp_commit();
        }

        const bool diag = (kb == qb_local);
#pragma unroll
        for (int nj = 0; nj < 4; nj++) {
            int mloc = warp_m * 16 + qrow;
            int cloc = warp_n * 32 + nj * 8 + qcol;
            float v0 = sacc[nj][0] * SCALE;
            float v1 = sacc[nj][1] * SCALE;
            float v2 = sacc[nj][2] * SCALE;
            float v3 = sacc[nj][3] * SCALE;
            if (diag) {
                if (cloc     > mloc)     v0 = -1e30f;
                if (cloc + 1 > mloc)     v1 = -1e30f;
                if (cloc     > mloc + 8) v2 = -1e30f;
                if (cloc + 1 > mloc + 8) v3 = -1e30f;
            }
            Ss[mloc * 68 + cloc]           = v0;
            Ss[mloc * 68 + cloc + 1]       = v1;
            Ss[(mloc + 8) * 68 + cloc]     = v2;
            Ss[(mloc + 8) * 68 + cloc + 1] = v3;
        }
        __syncthreads();

        {
            float lmax = -INFINITY;
            int base = srow * 68 + sq * 16;
#pragma unroll
            for (int jj = 0; jj < 16; jj++)
                lmax = fmaxf(lmax, Ss[base + jj]);
            lmax = fmaxf(lmax, __shfl_xor_sync(0xffffffffu, lmax, 1));
            lmax = fmaxf(lmax, __shfl_xor_sync(0xffffffffu, lmax, 2));
            float m_new = fmaxf(m_run, lmax);
            float alpha = __expf(m_run - m_new);
            float lsum = 0.0f;
#pragma unroll
            for (int jj = 0; jj < 16; jj += 2) {
                float p0 = __expf(Ss[base + jj] - m_new);
                float p1 = __expf(Ss[base + jj + 1] - m_new);
                lsum += p0 + p1;
                int col = sq * 16 + jj;
                uint32_t byte = (uint32_t)(srow * 128) +
                    ((((col >> 3)) ^ (srow & 7)) << 4) + (col & 7) * 2;
                *(__half2*)(smc + ATT_PS + byte) = __floats2half2_rn(p0, p1);
            }
            lsum += __shfl_xor_sync(0xffffffffu, lsum, 1);
            lsum += __shfl_xor_sync(0xffffffffu, lsum, 2);
            l_run = l_run * alpha + lsum;
            m_run = m_new;
            if ((tid & 3) == 0) { alphas[srow] = alpha; lrow[srow] = l_run; }
        }
        __syncthreads();

        {
            float a0 = alphas[warp_m * 16 + qrow];
            float a1 = alphas[warp_m * 16 + qrow + 8];
#pragma unroll
            for (int nj = 0; nj < 8; nj++) {
                o[nj][0] *= a0; o[nj][1] *= a0;
                o[nj][2] *= a1; o[nj][3] *= a1;
            }
#pragma unroll
            for (int s4 = 0; s4 < 4; s4++) {
                uint32_t ap[4];
                ldsm4(ap, sbm + ATT_PS + swoff(a_row, (s4 << 1) + a_csel));
                uint32_t vh[4][4], vl[4][4];
#pragma unroll
                for (int nb = 0; nb < 4; nb++) {
                    uint32_t offv = cur * 16384 + warp_n * 8192 +
                        swoff(pb_row + nb * 16, (s4 << 1) + b_csel);
                    ldsm4(vh[nb], sbm + ATT_VHI + offv);
                    ldsm4(vl[nb], sbm + ATT_VLO + offv);
                }
#pragma unroll
                for (int nj = 0; nj < 8; nj++) {
                    const uint32_t* ph = &vh[nj >> 1][(nj & 1) * 2];
                    const uint32_t* pl = &vl[nj >> 1][(nj & 1) * 2];
                    mma16816(o[nj], ap, ph);
                    mma16816(o[nj], ap, pl);
                }
            }
        }
    }

    float inv0 = 1.0f / lrow[warp_m * 16 + qrow];
    float inv1 = 1.0f / lrow[warp_m * 16 + qrow + 8];
#pragma unroll
    for (int nj = 0; nj < 8; nj++) {
        int m = q_start + warp_m * 16 + qrow;
        int col = h * HD + warp_n * 64 + nj * 8 + qcol;
        *(__half2*)(oh + (size_t)m * DM + col) =
            __floats2half2_rn(o[nj][0] * inv0, o[nj][1] * inv0);
        *(__half2*)(oh + (size_t)(m + 8) * DM + col) =
            __floats2half2_rn(o[nj][2] * inv1, o[nj][3] * inv1);
    }
}

// ============================================================================
// launch
// ============================================================================
extern "C" void kernel_launch(void* const* d_in, const int* in_sizes, int n_in,
                              void* d_out, int out_size)
{
    const float* hs    = (const float*)d_in[0];
    const float* w_qkv = (const float*)d_in[1];
    const float* w_o   = (const float*)d_in[2];
    const float* cs    = (const float*)d_in[3];
    const float* sn    = (const float*)d_in[4];
    (void)in_sizes; (void)n_in;

    __half *ah, *bhi, *blo, *bohi, *qhi, *qlo, *khi, *klo, *vthi, *vtlo;
    cudaGetSymbolAddress((void**)&ah, g_ah);
    cudaGetSymbolAddress((void**)&bhi, g_bhi);
    cudaGetSymbolAddress((void**)&blo, g_blo);
    cudaGetSymbolAddress((void**)&bohi, g_bohi);
    cudaGetSymbolAddress((void**)&qhi, g_qhi);
    cudaGetSymbolAddress((void**)&qlo, g_qlo);
    cudaGetSymbolAddress((void**)&khi, g_khi);
    cudaGetSymbolAddress((void**)&klo, g_klo);
    cudaGetSymbolAddress((void**)&vthi, g_vthi);
    cudaGetSymbolAddress((void**)&vtlo, g_vtlo);

    static cudaStream_t s1 = nullptr, s2 = nullptr;
    static cudaEvent_t eFork = nullptr, eWqkv = nullptr, eWo = nullptr;
    static int init_done = 0;
    if (!init_done) {
        cudaFuncSetAttribute(attn_kernel, cudaFuncAttributeMaxDynamicSharedMemorySize,
                             ATT_SMEM);
        cudaFuncSetAttribute(gemm_tc_kernel<0>,
                             cudaFuncAttributeMaxDynamicSharedMemorySize, GEMM_SMEM);
        cudaFuncSetAttribute(gemm_tc_kernel<1>,
                             cudaFuncAttributeMaxDynamicSharedMemorySize, GEMM_SMEM);
        cudaFuncSetAttribute(gemm1p_kernel,
                             cudaFuncAttributeMaxDynamicSharedMemorySize, GEMM1P_SMEM);
        cudaStreamCreateWithFlags(&s1, cudaStreamNonBlocking);
        cudaStreamCreateWithFlags(&s2, cudaStreamNonBlocking);
        cudaEventCreateWithFlags(&eFork, cudaEventDisableTiming);
        cudaEventCreateWithFlags(&eWqkv, cudaEventDisableTiming);
        cudaEventCreateWithFlags(&eWo, cudaEventDisableTiming);
        init_done = 1;
    }

    cudaEventRecord(eFork, 0);
    cudaStreamWaitEvent(s1, eFork, 0);
    cudaStreamWaitEvent(s2, eFork, 0);

    split_kernel<<<(QKV_N * DM / 8) / 256, 256, 0, s1>>>(
        w_qkv, bhi, blo, QKV_N * DM / 8);
    cudaEventRecord(eWqkv, s1);

    // w_o: single fp16 (1-pass O-projection) — overlaps GEMM1
    cvt_half_kernel<<<(DM * DM / 8) / 256, 256, 0, s2>>>(w_o, bohi, DM * DM / 8);
    cudaEventRecord(eWo, s2);

    cvt_half_kernel<<<(T_TOK * DM / 8) / 256, 256>>>(hs, ah, T_TOK * DM / 8);
    cudaStreamWaitEvent(0, eWqkv, 0);

    // QKV projection with fused clip+RoPE+split / V-transpose epilogue
    gemm_tc_kernel<1><<<dim3(QKV_N / 128, T_TOK / 128), 256, GEMM_SMEM>>>(
        ah, bhi, blo, nullptr, QKV_N, cs, sn,
        qhi, qlo, khi, klo, vthi, vtlo);

    // tensor-core flash attention -> fp16 O into g_ah
    attn_kernel<<<dim3(32, NH), 256, ATT_SMEM>>>(qhi, qlo, khi, klo, vthi, vtlo, ah);

    // output projection (1-pass fp16)
    cudaStreamWaitEvent(0, eWo, 0);
    gemm1p_kernel<<<dim3(DM / 128, T_TOK / 128), 256, GEMM1P_SMEM>>>(
        ah, bohi, (float*)d_out, DM);
}

// round 14
// speedup vs baseline: 2.1161x; 1.4136x over previous
#include <cuda_runtime.h>
#include <cuda_fp16.h>
#include <math.h>
#include <cstdint>

// ---------------- problem constants ----------------
#define T_TOK   2048
#define DM      4096
#define NH      32
#define KVH     8
#define HD      128
#define QKV_N   6144
#define CLIPV   8.0f
#define SCALE   0.08838834764831845f
#define KTOT    4096

// ---------------- scratch ----------------
__device__ __align__(16) __half g_ah  [T_TOK * DM];
__device__ __align__(16) __half g_bq  [QKV_N * DM];   // w_qkv fp16
__device__ __align__(16) __half g_bo  [DM * DM];      // w_o fp16
__device__ __align__(16) __half g_qhi[T_TOK * DM];
__device__ __align__(16) __half g_qlo[T_TOK * DM];
__device__ __align__(16) __half g_khi[T_TOK * KVH * HD];
__device__ __align__(16) __half g_klo[T_TOK * KVH * HD];
__device__ __align__(16) __half g_vthi[KVH * HD * T_TOK];
__device__ __align__(16) __half g_vtlo[KVH * HD * T_TOK];

// ============================ PTX helpers ============================
__device__ __forceinline__ uint32_t smem_u32_of(const void* p) {
    uint32_t a;
    asm("{ .reg .u64 t; cvta.to.shared.u64 t, %1; cvt.u32.u64 %0, t; }"
        : "=r"(a) : "l"(p));
    return a;
}
__device__ __forceinline__ void cp_async16(uint32_t dst, const void* src) {
    asm volatile("cp.async.cg.shared.global [%0], [%1], 16;" :: "r"(dst), "l"(src));
}
__device__ __forceinline__ void cp_commit() {
    asm volatile("cp.async.commit_group;" ::: "memory");
}
template<int N> __device__ __forceinline__ void cp_wait() {
    asm volatile("cp.async.wait_group %0;" :: "n"(N) : "memory");
}
__device__ __forceinline__ void ldsm4(uint32_t (&r)[4], uint32_t addr) {
    asm volatile("ldmatrix.sync.aligned.m8n8.x4.shared.b16 {%0,%1,%2,%3}, [%4];"
        : "=r"(r[0]), "=r"(r[1]), "=r"(r[2]), "=r"(r[3]) : "r"(addr));
}
__device__ __forceinline__ void mma16816(float (&d)[4], const uint32_t (&a)[4],
                                         const uint32_t* b) {
    asm volatile("mma.sync.aligned.m16n8k16.row.col.f32.f16.f16.f32 "
        "{%0,%1,%2,%3}, {%4,%5,%6,%7}, {%8,%9}, {%0,%1,%2,%3};"
        : "+f"(d[0]), "+f"(d[1]), "+f"(d[2]), "+f"(d[3])
        : "r"(a[0]), "r"(a[1]), "r"(a[2]), "r"(a[3]), "r"(b[0]), "r"(b[1]));
}
__device__ __forceinline__ uint32_t swoff(int row, int cch) {
    return (uint32_t)(row * 128 + (((cch) ^ (row & 7)) << 4));
}
__device__ __forceinline__ float clipf(float v) {
    return fminf(CLIPV, fmaxf(-CLIPV, v));
}

// ============================================================================
// convert fp32 -> fp16 (8 elems/thread)
// ============================================================================
__global__ void __launch_bounds__(256) cvt_half_kernel(
    const float* __restrict__ in, __half* __restrict__ out, int n8)
{
    int i = blockIdx.x * 256 + threadIdx.x;
    if (i >= n8) return;
    float4 v0 = ((const float4*)in)[2 * i];
    float4 v1 = ((const float4*)in)[2 * i + 1];
    float a[8] = {v0.x, v0.y, v0.z, v0.w, v1.x, v1.y, v1.z, v1.w};
    __half h[8];
#pragma unroll
    for (int j = 0; j < 8; j++) h[j] = __float2half(a[j]);
    ((uint4*)out)[i] = *(uint4*)h;
}

// ============================================================================
// HMMA GEMM, 1-pass fp16 AxB. 128x128 tile, BK=64, 8 warps, 3x32KB stages,
// occ 2. FUSED=1: QKV epilogue (clip + RoPE/split Q,K + transpose/split V).
// ============================================================================
#define STAGE1P_BYTES 32768
#define GEMM1P_SMEM   (3 * STAGE1P_BYTES)
#define NCHUNK        (KTOT / 64)

template<int FUSED>
__global__ void __launch_bounds__(256, 2) gemm1p_kernel(
    const __half* __restrict__ Ah, const __half* __restrict__ B,
    float* __restrict__ C, int Ntot,
    const float* __restrict__ cs_, const float* __restrict__ sn_,
    __half* __restrict__ Qhi, __half* __restrict__ Qlo,
    __half* __restrict__ Khi, __half* __restrict__ Klo,
    __half* __restrict__ Vthi, __half* __restrict__ Vtlo)
{
    extern __shared__ char smem[];
    const uint32_t sb = smem_u32_of(smem);
    const int tid  = threadIdx.x;
    const int wid  = tid >> 5;
    const int lane = tid & 31;
    const int warp_m = wid >> 2;
    const int warp_n = wid & 3;
    const int m0 = blockIdx.y * 128;
    const int n0 = blockIdx.x * 128;

    const int g = lane >> 3, r = lane & 7;
    const int a_row  = warp_m * 64 + (g & 1) * 8 + r;
    const int a_csel = g >> 1;
    const int b_row  = warp_n * 32 + (g >> 1) * 8 + r;
    const int b_csel = g & 1;

    float acc[4][4][4];
#pragma unroll
    for (int i = 0; i < 4; i++)
#pragma unroll
        for (int j = 0; j < 4; j++)
#pragma unroll
            for (int k = 0; k < 4; k++) acc[i][j][k] = 0.0f;

#define LOAD_CHUNK1P(cc, ss) do { \
    const int k0_ = (cc) * 64; \
    const uint32_t sbase_ = sb + (ss) * STAGE1P_BYTES; \
    _Pragma("unroll") \
    for (int t_ = 0; t_ < 8; t_++) { \
        int id_ = tid + t_ * 256; \
        int tile_ = id_ >> 10; \
        int w_ = id_ & 1023; \
        int mrow_ = w_ >> 3; \
        int cch_ = w_ & 7; \
        const __half* base_ = tile_ ? B : Ah; \
        int grow_ = (tile_ == 0) ? (m0 + mrow_) : (n0 + mrow_); \
        uint32_t dst_ = sbase_ + tile_ * 16384 + mrow_ * 128 + ((cch_ ^ (mrow_ & 7)) << 4); \
        cp_async16(dst_, base_ + (size_t)grow_ * KTOT + k0_ + cch_ * 8); \
    } \
    cp_commit(); \
} while (0)

    LOAD_CHUNK1P(0, 0);
    LOAD_CHUNK1P(1, 1);

    int stage = 0, lstage = 2;
    for (int c = 0; c < NCHUNK; c++) {
        if (c == NCHUNK - 1) cp_wait<0>(); else cp_wait<1>();
        __syncthreads();

        if (c + 2 < NCHUNK) LOAD_CHUNK1P(c + 2, lstage);

        const uint32_t st = sb + stage * STAGE1P_BYTES;
#pragma unroll
        for (int s = 0; s < 4; s++) {
            uint32_t a_f[4][4];
#pragma unroll
            for (int mi = 0; mi < 4; mi++) {
                int m = a_row + mi * 16;
                uint32_t off = (uint32_t)(m * 128) +
                               ((((s << 1) + a_csel) ^ (m & 7)) << 4);
                ldsm4(a_f[mi], st + off);
            }
            uint32_t b_f[2][4];
#pragma unroll
            for (int j = 0; j < 2; j++) {
                int n = b_row + j * 16;
                uint32_t off = (uint32_t)(n * 128) +
                               ((((s << 1) + b_csel) ^ (n & 7)) << 4);
                ldsm4(b_f[j], st + 16384 + off);
            }
#pragma unroll
            for (int mi = 0; mi < 4; mi++) {
#pragma unroll
                for (int nj = 0; nj < 4; nj++) {
                    mma16816(acc[mi][nj], a_f[mi], &b_f[nj >> 1][(nj & 1) * 2]);
                }
            }
        }
        stage = (stage == 2) ? 0 : stage + 1;
        lstage = (lstage == 2) ? 0 : lstage + 1;
    }

    const int qrow = lane >> 2;
    const int qcol = (lane & 3) * 2;

    if (!FUSED) {
#pragma unroll
        for (int mi = 0; mi < 4; mi++) {
#pragma unroll
            for (int nj = 0; nj < 4; nj++) {
                int m = m0 + warp_m * 64 + mi * 16 + qrow;
                int n = n0 + warp_n * 32 + nj * 8 + qcol;
                *(float2*)(C + (size_t)m * Ntot + n) =
                    make_float2(acc[mi][nj][0], acc[mi][nj][1]);
                *(float2*)(C + (size_t)(m + 8) * Ntot + n) =
                    make_float2(acc[mi][nj][2], acc[mi][nj][3]);
            }
        }
        return;
    }

    // ---- FUSED QKV epilogue: stage clipped tile in smem ----
    __syncthreads();
    float* Cs = (float*)smem;   // [128][132] = 67.6KB < 96KB
#pragma unroll
    for (int mi = 0; mi < 4; mi++) {
#pragma unroll
        for (int nj = 0; nj < 4; nj++) {
            int rr = warp_m * 64 + mi * 16 + qrow;
            int cc = warp_n * 32 + nj * 8 + qcol;
            Cs[rr * 132 + cc]           = clipf(acc[mi][nj][0]);
            Cs[rr * 132 + cc + 1]       = clipf(acc[mi][nj][1]);
            Cs[(rr + 8) * 132 + cc]     = clipf(acc[mi][nj][2]);
            Cs[(rr + 8) * 132 + cc + 1] = clipf(acc[mi][nj][3]);
        }
    }
    __syncthreads();

    const int head = n0 >> 7;
    if (head < NH + KVH) {
        __half *hi, *lo;
        size_t rowstride;
        int coff;
        if (head < NH) {
            hi = Qhi; lo = Qlo; rowstride = DM; coff = head * HD;
        } else {
            hi = Khi; lo = Klo; rowstride = KVH * HD; coff = (head - NH) * HD;
        }
        const int dp = (tid & 31) * 2;
        const int r0 = tid >> 5;
#pragma unroll
        for (int it = 0; it < 16; it++) {
            int row = it * 8 + r0;
            int tok = m0 + row;
            float c0 = cs_[tok * 64 + dp],     c1 = cs_[tok * 64 + dp + 1];
            float s0 = sn_[tok * 64 + dp],     s1 = sn_[tok * 64 + dp + 1];
            float x10 = Cs[row * 132 + dp],      x11 = Cs[row * 132 + dp + 1];
            float x20 = Cs[row * 132 + dp + 64], x21 = Cs[row * 132 + dp + 65];
            float y10 = x10 * c0 - x20 * s0, y11 = x11 * c1 - x21 * s1;
            float y20 = x20 * c0 + x10 * s0, y21 = x21 * c1 + x11 * s1;
            __half h10 = __float2half(y10), h11 = __float2half(y11);
            __half h20 = __float2half(y20), h21 = __float2half(y21);
            __half l10 = __float2half(y10 - __half2float(h10));
            __half l11 = __float2half(y11 - __half2float(h11));
            __half l20 = __float2half(y20 - __half2float(h20));
            __half l21 = __float2half(y21 - __half2float(h21));
            size_t ob = (size_t)tok * rowstride + coff;
            *(__half2*)(hi + ob + dp)      = __halves2half2(h10, h11);
            *(__half2*)(hi + ob + dp + 64) = __halves2half2(h20, h21);
            *(__half2*)(lo + ob + dp)      = __halves2half2(l10, l11);
            *(__half2*)(lo + ob + dp + 64) = __halves2half2(l20, l21);
        }
    } else {
        const int kvh = head - NH - KVH;
        const int d = tid & 127;
        const int hsel = tid >> 7;
        size_t obase = ((size_t)kvh * HD + d) * T_TOK + m0 + hsel * 64;
#pragma unroll
        for (int gb = 0; gb < 8; gb++) {
            __half hb[8], lb[8];
#pragma unroll
            for (int u = 0; u < 8; u++) {
                float v = Cs[(hsel * 64 + gb * 8 + u) * 132 + d];
                hb[u] = __float2half(v);
                lb[u] = __float2half(v - __half2float(hb[u]));
            }
            *(uint4*)(Vthi + obase + gb * 8) = *(uint4*)hb;
            *(uint4*)(Vtlo + obase + gb * 8) = *(uint4*)lb;
        }
    }
}

// ============================================================================
// Tensor-core flash attention (R13 proven)
// ============================================================================
#define ATT_QHI 0
#define ATT_QLO 16384
#define ATT_KHI 32768
#define ATT_KLO 65536
#define ATT_VHI 98304
#define ATT_VLO 131072
#define ATT_PS  163840
#define ATT_SS  172032
#define ATT_ALPHA (ATT_SS + 17408)
#define ATT_LROW  (ATT_ALPHA + 256)
#define ATT_SMEM  (ATT_LROW + 256)

__global__ void __launch_bounds__(256) attn_kernel(
    const __half* __restrict__ Qhi, const __half* __restrict__ Qlo,
    const __half* __restrict__ Khi, const __half* __restrict__ Klo,
    const __half* __restrict__ Vthi, const __half* __restrict__ Vtlo,
    __half* __restrict__ oh)
{
    extern __shared__ char smc[];
    const uint32_t sbm = smem_u32_of(smc);
    float* Ss     = (float*)(smc + ATT_SS);
    float* alphas = (float*)(smc + ATT_ALPHA);
    float* lrow   = (float*)(smc + ATT_LROW);

    const int tid = threadIdx.x;
    const int h   = blockIdx.y;
    const int qb  = blockIdx.x;

    int seq, qb_local;
    if      (qb < 8)  { seq = 0; qb_local = qb; }
    else if (qb < 20) { seq = 1; qb_local = qb - 8; }
    else if (qb < 26) { seq = 2; qb_local = qb - 20; }
    else              { seq = 3; qb_local = qb - 26; }
    const int cu[4] = {0, 512, 1280, 1664};
    const int seq_start = cu[seq];
    const int q_start = seq_start + qb_local * 64;
    const int kh = h >> 2;

    const int wid = tid >> 5, lane = tid & 31;
    const int warp_m = wid & 3;
    const int warp_n = wid >> 2;
    const int g = lane >> 3, r = lane & 7;
    const int a_row  = warp_m * 16 + (g & 1) * 8 + r;
    const int a_csel = g >> 1;
    const int b_row  = warp_n * 32 + (g >> 1) * 8 + r;
    const int b_csel = g & 1;
    const int pb_row = (g >> 1) * 8 + r;
    const int qrow = lane >> 2, qcol = (lane & 3) * 2;
    const int srow = tid >> 2, sq = tid & 3;

#define LOAD_KV(tok0_, bb_) do { \
    _Pragma("unroll") \
    for (int t = 0; t < 8; t++) { \
        int id = tid + t * 256; \
        int buf = id >> 10; \
        int w = id & 1023; \
        int half_ = w >> 9; \
        int w2 = w & 511; \
        int trow = w2 >> 3, cch = w2 & 7; \
        const __half* src = (buf ? Klo : Khi) + \
            (size_t)((tok0_) + trow) * (KVH * HD) + kh * HD + half_ * 64 + cch * 8; \
        uint32_t dst = sbm + (buf ? ATT_KLO : ATT_KHI) + (bb_) * 16384 + \
                       half_ * 8192 + swoff(trow, cch); \
        cp_async16(dst, src); \
    } \
    _Pragma("unroll") \
    for (int t = 0; t < 8; t++) { \
        int id = tid + t * 256; \
        int buf = id >> 10; \
        int w = id & 1023; \
        int drow = w >> 3, cch = w & 7; \
        int half_ = drow >> 6, rl = drow & 63; \
        const __half* src = (buf ? Vtlo : Vthi) + \
            ((size_t)kh * HD + drow) * T_TOK + (tok0_) + cch * 8; \
        uint32_t dst = sbm + (buf ? ATT_VLO : ATT_VHI) + (bb_) * 16384 + \
                       half_ * 8192 + swoff(rl, cch); \
        cp_async16(dst, src); \
    } \
} while (0)

#pragma unroll
    for (int t = 0; t < 8; t++) {
        int id = tid + t * 256;
        int buf = id >> 10;
        int w = id & 1023;
        int half_ = w >> 9;
        int w2 = w & 511;
        int trow = w2 >> 3, cch = w2 & 7;
        const __half* src = (buf ? Qlo : Qhi) +
            (size_t)(q_start + trow) * DM + h * HD + half_ * 64 + cch * 8;
        uint32_t dst = sbm + (buf ? ATT_QLO : ATT_QHI) + half_ * 8192 + swoff(trow, cch);
        cp_async16(dst, src);
    }
    LOAD_KV(seq_start, 0);
    cp_commit();

    float m_run = -INFINITY, l_run = 0.0f;
    float o[8][4];
#pragma unroll
    for (int i = 0; i < 8; i++)
#pragma unroll
        for (int j = 0; j < 4; j++) o[i][j] = 0.0f;

    for (int kb = 0; kb <= qb_local; kb++) {
        const int cur = kb & 1;
        cp_wait<0>();
        __syncthreads();

        float sacc[4][4];
#pragma unroll
        for (int i = 0; i < 4; i++)
#pragma unroll
            for (int j = 0; j < 4; j++) sacc[i][j] = 0.0f;

#pragma unroll
        for (int half_ = 0; half_ < 2; half_++) {
#pragma unroll
            for (int s4 = 0; s4 < 4; s4++) {
                uint32_t offa = half_ * 8192 + swoff(a_row, (s4 << 1) + a_csel);
                uint32_t ah4[4], al4[4];
                ldsm4(ah4, sbm + ATT_QHI + offa);
                ldsm4(al4, sbm + ATT_QLO + offa);
                uint32_t bh[2][4], bl[2][4];
#pragma unroll
                for (int jb = 0; jb < 2; jb++) {
                    uint32_t offb = cur * 16384 + half_ * 8192 +
                                    swoff(b_row + jb * 16, (s4 << 1) + b_csel);
                    ldsm4(bh[jb], sbm + ATT_KHI + offb);
                    ldsm4(bl[jb], sbm + ATT_KLO + offb);
                }
#pragma unroll
                for (int nj = 0; nj < 4; nj++) {
                    const uint32_t* ph = &bh[nj >> 1][(nj & 1) * 2];
                    const uint32_t* pl = &bl[nj >> 1][(nj & 1) * 2];
                    mma16816(sacc[nj], ah4, ph);
                    mma16816(sacc[nj], ah4, pl);
                    mma16816(sacc[nj], al4, ph);
                }
            }
        }

        if (kb < qb_local) {
            LOAD_KV(seq_start + (kb + 1) * 64, cur ^ 1);
            cp_commit();
        }

        const bool diag = (kb == qb_local);
#pragma unroll
        for (int nj = 0; nj < 4; nj++) {
            int mloc = warp_m * 16 + qrow;
            int cloc = warp_n * 32 + nj * 8 + qcol;
            float v0 = sacc[nj][0] * SCALE;
            float v1 = sacc[nj][1] * SCALE;
            float v2 = sacc[nj][2] * SCALE;
            float v3 = sacc[nj][3] * SCALE;
            if (diag) {
                if (cloc     > mloc)     v0 = -1e30f;
                if (cloc + 1 > mloc)     v1 = -1e30f;
                if (cloc     > mloc + 8) v2 = -1e30f;
                if (cloc + 1 > mloc + 8) v3 = -1e30f;
            }
            Ss[mloc * 68 + cloc]           = v0;
            Ss[mloc * 68 + cloc + 1]       = v1;
            Ss[(mloc + 8) * 68 + cloc]     = v2;
            Ss[(mloc + 8) * 68 + cloc + 1] = v3;
        }
        __syncthreads();

        {
            float lmax = -INFINITY;
            int base = srow * 68 + sq * 16;
#pragma unroll
            for (int jj = 0; jj < 16; jj++)
                lmax = fmaxf(lmax, Ss[base + jj]);
            lmax = fmaxf(lmax, __shfl_xor_sync(0xffffffffu, lmax, 1));
            lmax = fmaxf(lmax, __shfl_xor_sync(0xffffffffu, lmax, 2));
            float m_new = fmaxf(m_run, lmax);
            float alpha = __expf(m_run - m_new);
            float lsum = 0.0f;
#pragma unroll
            for (int jj = 0; jj < 16; jj += 2) {
                float p0 = __expf(Ss[base + jj] - m_new);
                float p1 = __expf(Ss[base + jj + 1] - m_new);
                lsum += p0 + p1;
                int col = sq * 16 + jj;
                uint32_t byte = (uint32_t)(srow * 128) +
                    ((((col >> 3)) ^ (srow & 7)) << 4) + (col & 7) * 2;
                *(__half2*)(smc + ATT_PS + byte) = __floats2half2_rn(p0, p1);
            }
            lsum += __shfl_xor_sync(0xffffffffu, lsum, 1);
            lsum += __shfl_xor_sync(0xffffffffu, lsum, 2);
            l_run = l_run * alpha + lsum;
            m_run = m_new;
            if ((tid & 3) == 0) { alphas[srow] = alpha; lrow[srow] = l_run; }
        }
        __syncthreads();

        {
            float a0 = alphas[warp_m * 16 + qrow];
            float a1 = alphas[warp_m * 16 + qrow + 8];
#pragma unroll
            for (int nj = 0; nj < 8; nj++) {
                o[nj][0] *= a0; o[nj][1] *= a0;
                o[nj][2] *= a1; o[nj][3] *= a1;
            }
#pragma unroll
            for (int s4 = 0; s4 < 4; s4++) {
                uint32_t ap[4];
                ldsm4(ap, sbm + ATT_PS + swoff(a_row, (s4 << 1) + a_csel));
                uint32_t vh[4][4], vl[4][4];
#pragma unroll
                for (int nb = 0; nb < 4; nb++) {
                    uint32_t offv = cur * 16384 + warp_n * 8192 +
                        swoff(pb_row + nb * 16, (s4 << 1) + b_csel);
                    ldsm4(vh[nb], sbm + ATT_VHI + offv);
                    ldsm4(vl[nb], sbm + ATT_VLO + offv);
                }
#pragma unroll
                for (int nj = 0; nj < 8; nj++) {
                    const uint32_t* ph = &vh[nj >> 1][(nj & 1) * 2];
                    const uint32_t* pl = &vl[nj >> 1][(nj & 1) * 2];
                    mma16816(o[nj], ap, ph);
                    mma16816(o[nj], ap, pl);
                }
            }
        }
    }

    float inv0 = 1.0f / lrow[warp_m * 16 + qrow];
    float inv1 = 1.0f / lrow[warp_m * 16 + qrow + 8];
#pragma unroll
    for (int nj = 0; nj < 8; nj++) {
        int m = q_start + warp_m * 16 + qrow;
        int col = h * HD + warp_n * 64 + nj * 8 + qcol;
        *(__half2*)(oh + (size_t)m * DM + col) =
            __floats2half2_rn(o[nj][0] * inv0, o[nj][1] * inv0);
        *(__half2*)(oh + (size_t)(m + 8) * DM + col) =
            __floats2half2_rn(o[nj][2] * inv1, o[nj][3] * inv1);
    }
}

// ============================================================================
// launch
// ============================================================================
extern "C" void kernel_launch(void* const* d_in, const int* in_sizes, int n_in,
                              void* d_out, int out_size)
{
    const float* hs    = (const float*)d_in[0];
    const float* w_qkv = (const float*)d_in[1];
    const float* w_o   = (const float*)d_in[2];
    const float* cs    = (const float*)d_in[3];
    const float* sn    = (const float*)d_in[4];
    (void)in_sizes; (void)n_in;

    __half *ah, *bq, *bo, *qhi, *qlo, *khi, *klo, *vthi, *vtlo;
    cudaGetSymbolAddress((void**)&ah, g_ah);
    cudaGetSymbolAddress((void**)&bq, g_bq);
    cudaGetSymbolAddress((void**)&bo, g_bo);
    cudaGetSymbolAddress((void**)&qhi, g_qhi);
    cudaGetSymbolAddress((void**)&qlo, g_qlo);
    cudaGetSymbolAddress((void**)&khi, g_khi);
    cudaGetSymbolAddress((void**)&klo, g_klo);
    cudaGetSymbolAddress((void**)&vthi, g_vthi);
    cudaGetSymbolAddress((void**)&vtlo, g_vtlo);

    static cudaStream_t s1 = nullptr, s2 = nullptr;
    static cudaEvent_t eFork = nullptr, eWqkv = nullptr, eWo = nullptr;
    static int init_done = 0;
    if (!init_done) {
        cudaFuncSetAttribute(attn_kernel, cudaFuncAttributeMaxDynamicSharedMemorySize,
                             ATT_SMEM);
        cudaFuncSetAttribute(gemm1p_kernel<0>,
                             cudaFuncAttributeMaxDynamicSharedMemorySize, GEMM1P_SMEM);
        cudaFuncSetAttribute(gemm1p_kernel<1>,
                             cudaFuncAttributeMaxDynamicSharedMemorySize, GEMM1P_SMEM);
        cudaStreamCreateWithFlags(&s1, cudaStreamNonBlocking);
        cudaStreamCreateWithFlags(&s2, cudaStreamNonBlocking);
        cudaEventCreateWithFlags(&eFork, cudaEventDisableTiming);
        cudaEventCreateWithFlags(&eWqkv, cudaEventDisableTiming);
        cudaEventCreateWithFlags(&eWo, cudaEventDisableTiming);
        init_done = 1;
    }

    cudaEventRecord(eFork, 0);
    cudaStreamWaitEvent(s1, eFork, 0);
    cudaStreamWaitEvent(s2, eFork, 0);

    // w_qkv -> fp16 (1-pass GEMM1)
    cvt_half_kernel<<<(QKV_N * DM / 8) / 256, 256, 0, s1>>>(w_qkv, bq, QKV_N * DM / 8);
    cudaEventRecord(eWqkv, s1);

    // w_o -> fp16 (1-pass O-projection) — overlaps GEMM1
    cvt_half_kernel<<<(DM * DM / 8) / 256, 256, 0, s2>>>(w_o, bo, DM * DM / 8);
    cudaEventRecord(eWo, s2);

    cvt_half_kernel<<<(T_TOK * DM / 8) / 256, 256>>>(hs, ah, T_TOK * DM / 8);
    cudaStreamWaitEvent(0, eWqkv, 0);

    // QKV projection (1-pass) with fused clip+RoPE+split / V-transpose epilogue
    gemm1p_kernel<1><<<dim3(QKV_N / 128, T_TOK / 128), 256, GEMM1P_SMEM>>>(
        ah, bq, nullptr, QKV_N, cs, sn, qhi, qlo, khi, klo, vthi, vtlo);

    // tensor-core flash attention -> fp16 O into g_ah
    attn_kernel<<<dim3(32, NH), 256, ATT_SMEM>>>(qhi, qlo, khi, klo, vthi, vtlo, ah);

    // output projection (1-pass)
    cudaStreamWaitEvent(0, eWo, 0);
    gemm1p_kernel<0><<<dim3(DM / 128, T_TOK / 128), 256, GEMM1P_SMEM>>>(
        ah, bo, (float*)d_out, DM, nullptr, nullptr,
        nullptr, nullptr, nullptr, nullptr, nullptr, nullptr);
}

// round 17
// speedup vs baseline: 2.2378x; 1.0575x over previous
#include <cuda_runtime.h>
#include <cuda_fp16.h>
#include <math.h>
#include <cstdint>

// ---------------- problem constants ----------------
#define T_TOK   2048
#define DM      4096
#define NH      32
#define KVH     8
#define HD      128
#define QKV_N   6144
#define CLIPV   8.0f
#define SCALE   0.08838834764831845f
#define KTOT    4096

// ---------------- scratch ----------------
__device__ __align__(16) __half g_ah  [T_TOK * DM];
__device__ __align__(16) __half g_bq  [QKV_N * DM];
__device__ __align__(16) __half g_bo  [DM * DM];
__device__ __align__(16) __half g_qh [T_TOK * DM];           // Q fp16 (hi only)
__device__ __align__(16) __half g_khi[T_TOK * KVH * HD];
__device__ __align__(16) __half g_klo[T_TOK * KVH * HD];
__device__ __align__(16) __half g_vthi[KVH * HD * T_TOK];
__device__ __align__(16) __half g_vtlo[KVH * HD * T_TOK];

// heavy-first attention qb order (sorted by qb_local desc)
__device__ const int g_qb_order[32] = {
    19, 18, 17, 16, 15, 7, 14, 6, 13, 5, 25, 31, 12, 4, 24, 30,
    11, 3, 23, 29, 10, 2, 22, 28, 9, 1, 21, 27, 8, 0, 20, 26
};

// ============================ PTX helpers ============================
__device__ __forceinline__ uint32_t smem_u32_of(const void* p) {
    uint32_t a;
    asm("{ .reg .u64 t; cvta.to.shared.u64 t, %1; cvt.u32.u64 %0, t; }"
        : "=r"(a) : "l"(p));
    return a;
}
__device__ __forceinline__ void cp_async16(uint32_t dst, const void* src) {
    asm volatile("cp.async.cg.shared.global [%0], [%1], 16;" :: "r"(dst), "l"(src));
}
__device__ __forceinline__ void cp_commit() {
    asm volatile("cp.async.commit_group;" ::: "memory");
}
template<int N> __device__ __forceinline__ void cp_wait() {
    asm volatile("cp.async.wait_group %0;" :: "n"(N) : "memory");
}
__device__ __forceinline__ void ldsm4(uint32_t (&r)[4], uint32_t addr) {
    asm volatile("ldmatrix.sync.aligned.m8n8.x4.shared.b16 {%0,%1,%2,%3}, [%4];"
        : "=r"(r[0]), "=r"(r[1]), "=r"(r[2]), "=r"(r[3]) : "r"(addr));
}
__device__ __forceinline__ void mma16816(float (&d)[4], const uint32_t (&a)[4],
                                         const uint32_t* b) {
    asm volatile("mma.sync.aligned.m16n8k16.row.col.f32.f16.f16.f32 "
        "{%0,%1,%2,%3}, {%4,%5,%6,%7}, {%8,%9}, {%0,%1,%2,%3};"
        : "+f"(d[0]), "+f"(d[1]), "+f"(d[2]), "+f"(d[3])
        : "r"(a[0]), "r"(a[1]), "r"(a[2]), "r"(a[3]), "r"(b[0]), "r"(b[1]));
}
__device__ __forceinline__ uint32_t swoff(int row, int cch) {
    return (uint32_t)(row * 128 + (((cch) ^ (row & 7)) << 4));
}
__device__ __forceinline__ float clipf(float v) {
    return fminf(CLIPV, fmaxf(-CLIPV, v));
}

// ============================================================================
// convert fp32 -> fp16 (8 elems/thread)
// ============================================================================
__global__ void __launch_bounds__(256) cvt_half_kernel(
    const float* __restrict__ in, __half* __restrict__ out, int n8)
{
    int i = blockIdx.x * 256 + threadIdx.x;
    if (i >= n8) return;
    float4 v0 = ((const float4*)in)[2 * i];
    float4 v1 = ((const float4*)in)[2 * i + 1];
    float a[8] = {v0.x, v0.y, v0.z, v0.w, v1.x, v1.y, v1.z, v1.w};
    __half h[8];
#pragma unroll
    for (int j = 0; j < 8; j++) h[j] = __float2half(a[j]);
    ((uint4*)out)[i] = *(uint4*)h;
}

// ============================================================================
// HMMA GEMM, 1-pass fp16 AxB (R14 proven). FUSED=1: QKV epilogue.
// ============================================================================
#define STAGE1P_BYTES 32768
#define GEMM1P_SMEM   (3 * STAGE1P_BYTES)
#define NCHUNK        (KTOT / 64)

template<int FUSED>
__global__ void __launch_bounds__(256, 2) gemm1p_kernel(
    const __half* __restrict__ Ah, const __half* __restrict__ B,
    float* __restrict__ C, int Ntot,
    const float* __restrict__ cs_, const float* __restrict__ sn_,
    __half* __restrict__ Qh,
    __half* __restrict__ Khi, __half* __restrict__ Klo,
    __half* __restrict__ Vthi, __half* __restrict__ Vtlo)
{
    extern __shared__ char smem[];
    const uint32_t sb = smem_u32_of(smem);
    const int tid  = threadIdx.x;
    const int wid  = tid >> 5;
    const int lane = tid & 31;
    const int warp_m = wid >> 2;
    const int warp_n = wid & 3;
    const int m0 = blockIdx.y * 128;
    const int n0 = blockIdx.x * 128;

    const int g = lane >> 3, r = lane & 7;
    const int a_row  = warp_m * 64 + (g & 1) * 8 + r;
    const int a_csel = g >> 1;
    const int b_row  = warp_n * 32 + (g >> 1) * 8 + r;
    const int b_csel = g & 1;

    float acc[4][4][4];
#pragma unroll
    for (int i = 0; i < 4; i++)
#pragma unroll
        for (int j = 0; j < 4; j++)
#pragma unroll
            for (int k = 0; k < 4; k++) acc[i][j][k] = 0.0f;

#define LOAD_CHUNK1P(cc, ss) do { \
    const int k0_ = (cc) * 64; \
    const uint32_t sbase_ = sb + (ss) * STAGE1P_BYTES; \
    _Pragma("unroll") \
    for (int t_ = 0; t_ < 8; t_++) { \
        int id_ = tid + t_ * 256; \
        int tile_ = id_ >> 10; \
        int w_ = id_ & 1023; \
        int mrow_ = w_ >> 3; \
        int cch_ = w_ & 7; \
        const __half* base_ = tile_ ? B : Ah; \
        int grow_ = (tile_ == 0) ? (m0 + mrow_) : (n0 + mrow_); \
        uint32_t dst_ = sbase_ + tile_ * 16384 + mrow_ * 128 + ((cch_ ^ (mrow_ & 7)) << 4); \
        cp_async16(dst_, base_ + (size_t)grow_ * KTOT + k0_ + cch_ * 8); \
    } \
    cp_commit(); \
} while (0)

    LOAD_CHUNK1P(0, 0);
    LOAD_CHUNK1P(1, 1);

    int stage = 0, lstage = 2;
    for (int c = 0; c < NCHUNK; c++) {
        if (c == NCHUNK - 1) cp_wait<0>(); else cp_wait<1>();
        __syncthreads();

        if (c + 2 < NCHUNK) LOAD_CHUNK1P(c + 2, lstage);

        const uint32_t st = sb + stage * STAGE1P_BYTES;
#pragma unroll
        for (int s = 0; s < 4; s++) {
            uint32_t a_f[4][4];
#pragma unroll
            for (int mi = 0; mi < 4; mi++) {
                int m = a_row + mi * 16;
                uint32_t off = (uint32_t)(m * 128) +
                               ((((s << 1) + a_csel) ^ (m & 7)) << 4);
                ldsm4(a_f[mi], st + off);
            }
            uint32_t b_f[2][4];
#pragma unroll
            for (int j = 0; j < 2; j++) {
                int n = b_row + j * 16;
                uint32_t off = (uint32_t)(n * 128) +
                               ((((s << 1) + b_csel) ^ (n & 7)) << 4);
                ldsm4(b_f[j], st + 16384 + off);
            }
#pragma unroll
            for (int mi = 0; mi < 4; mi++) {
#pragma unroll
                for (int nj = 0; nj < 4; nj++) {
                    mma16816(acc[mi][nj], a_f[mi], &b_f[nj >> 1][(nj & 1) * 2]);
                }
            }
        }
        stage = (stage == 2) ? 0 : stage + 1;
        lstage = (lstage == 2) ? 0 : lstage + 1;
    }

    const int qrow = lane >> 2;
    const int qcol = (lane & 3) * 2;

    if (!FUSED) {
#pragma unroll
        for (int mi = 0; mi < 4; mi++) {
#pragma unroll
            for (int nj = 0; nj < 4; nj++) {
                int m = m0 + warp_m * 64 + mi * 16 + qrow;
                int n = n0 + warp_n * 32 + nj * 8 + qcol;
                *(float2*)(C + (size_t)m * Ntot + n) =
                    make_float2(acc[mi][nj][0], acc[mi][nj][1]);
                *(float2*)(C + (size_t)(m + 8) * Ntot + n) =
                    make_float2(acc[mi][nj][2], acc[mi][nj][3]);
            }
        }
        return;
    }

    // ---- FUSED QKV epilogue ----
    __syncthreads();
    float* Cs = (float*)smem;   // [128][132]
#pragma unroll
    for (int mi = 0; mi < 4; mi++) {
#pragma unroll
        for (int nj = 0; nj < 4; nj++) {
            int rr = warp_m * 64 + mi * 16 + qrow;
            int cc = warp_n * 32 + nj * 8 + qcol;
            Cs[rr * 132 + cc]           = clipf(acc[mi][nj][0]);
            Cs[rr * 132 + cc + 1]       = clipf(acc[mi][nj][1]);
            Cs[(rr + 8) * 132 + cc]     = clipf(acc[mi][nj][2]);
            Cs[(rr + 8) * 132 + cc + 1] = clipf(acc[mi][nj][3]);
        }
    }
    __syncthreads();

    const int head = n0 >> 7;
    if (head < NH + KVH) {
        const bool isQ = (head < NH);
        __half* hi = isQ ? Qh : Khi;
        __half* lo = Klo;
        size_t rowstride = isQ ? DM : (KVH * HD);
        int coff = isQ ? head * HD : (head - NH) * HD;
        const int dp = (tid & 31) * 2;
        const int r0 = tid >> 5;
#pragma unroll
        for (int it = 0; it < 16; it++) {
            int row = it * 8 + r0;
            int tok = m0 + row;
            float c0 = cs_[tok * 64 + dp],     c1 = cs_[tok * 64 + dp + 1];
            float s0 = sn_[tok * 64 + dp],     s1 = sn_[tok * 64 + dp + 1];
            float x10 = Cs[row * 132 + dp],      x11 = Cs[row * 132 + dp + 1];
            float x20 = Cs[row * 132 + dp + 64], x21 = Cs[row * 132 + dp + 65];
            float y10 = x10 * c0 - x20 * s0, y11 = x11 * c1 - x21 * s1;
            float y20 = x20 * c0 + x10 * s0, y21 = x21 * c1 + x11 * s1;
            __half h10 = __float2half(y10), h11 = __float2half(y11);
            __half h20 = __float2half(y20), h21 = __float2half(y21);
            size_t ob = (size_t)tok * rowstride + coff;
            *(__half2*)(hi + ob + dp)      = __halves2half2(h10, h11);
            *(__half2*)(hi + ob + dp + 64) = __halves2half2(h20, h21);
            if (!isQ) {
                __half l10 = __float2half(y10 - __half2float(h10));
                __half l11 = __float2half(y11 - __half2float(h11));
                __half l20 = __float2half(y20 - __half2float(h20));
                __half l21 = __float2half(y21 - __half2float(h21));
                *(__half2*)(lo + ob + dp)      = __halves2half2(l10, l11);
                *(__half2*)(lo + ob + dp + 64) = __halves2half2(l20, l21);
            }
        }
    } else {
        const int kvh = head - NH - KVH;
        const int d = tid & 127;
        const int hsel = tid >> 7;
        size_t obase = ((size_t)kvh * HD + d) * T_TOK + m0 + hsel * 64;
#pragma unroll
        for (int gb = 0; gb < 8; gb++) {
            __half hb[8], lb[8];
#pragma unroll
            for (int u = 0; u < 8; u++) {
                float v = Cs[(hsel * 64 + gb * 8 + u) * 132 + d];
                hb[u] = __float2half(v);
                lb[u] = __float2half(v - __half2float(hb[u]));
            }
            *(uint4*)(Vthi + obase + gb * 8) = *(uint4*)hb;
            *(uint4*)(Vtlo + obase + gb * 8) = *(uint4*)lb;
        }
    }
}

// ============================================================================
// Tensor-core flash attention, occ 2 (single-buffered K/V, Q fp16 only).
// QK 2-pass (q*kh + q*kl), PV 2-pass.
// ============================================================================
#define ATT_Q    0
#define ATT_KHI  16384
#define ATT_KLO  32768
#define ATT_VHI  49152
#define ATT_VLO  65536
#define ATT_PS   81920
#define ATT_SS   90112
#define ATT_ALPHA (ATT_SS + 17408)
#define ATT_LROW  (ATT_ALPHA + 256)
#define ATT_SMEM  (ATT_LROW + 256)

__global__ void __launch_bounds__(256, 2) attn_kernel(
    const __half* __restrict__ Qh,
    const __half* __restrict__ Khi, const __half* __restrict__ Klo,
    const __half* __restrict__ Vthi, const __half* __restrict__ Vtlo,
    __half* __restrict__ oh)
{
    extern __shared__ char smc[];
    const uint32_t sbm = smem_u32_of(smc);
    float* Ss     = (float*)(smc + ATT_SS);
    float* alphas = (float*)(smc + ATT_ALPHA);
    float* lrow   = (float*)(smc + ATT_LROW);

    const int tid = threadIdx.x;
    const int h   = blockIdx.y;
    const int qb  = g_qb_order[blockIdx.x];

    int seq, qb_local;
    if      (qb < 8)  { seq = 0; qb_local = qb; }
    else if (qb < 20) { seq = 1; qb_local = qb - 8; }
    else if (qb < 26) { seq = 2; qb_local = qb - 20; }
    else              { seq = 3; qb_local = qb - 26; }
    const int cu[4] = {0, 512, 1280, 1664};
    const int seq_start = cu[seq];
    const int q_start = seq_start + qb_local * 64;
    const int kh = h >> 2;

    const int wid = tid >> 5, lane = tid & 31;
    const int warp_m = wid & 3;
    const int warp_n = wid >> 2;
    const int g = lane >> 3, r = lane & 7;
    const int a_row  = warp_m * 16 + (g & 1) * 8 + r;
    const int a_csel = g >> 1;
    const int b_row  = warp_n * 32 + (g >> 1) * 8 + r;
    const int b_csel = g & 1;
    const int pb_row = (g >> 1) * 8 + r;
    const int qrow = lane >> 2, qcol = (lane & 3) * 2;
    const int srow = tid >> 2, sq = tid & 3;

    // ---- preload Q (fp16 hi only, 16KB = 4 chunks/thread) ----
#pragma unroll
    for (int t = 0; t < 4; t++) {
        int w = tid + t * 256;                 // 0..1023
        int half_ = w >> 9;
        int w2 = w & 511;
        int trow = w2 >> 3, cch = w2 & 7;
        const __half* src = Qh +
            (size_t)(q_start + trow) * DM + h * HD + half_ * 64 + cch * 8;
        cp_async16(sbm + ATT_Q + half_ * 8192 + swoff(trow, cch), src);
    }
    cp_commit();

    float m_run = -INFINITY, l_run = 0.0f;
    float o[8][4];
#pragma unroll
    for (int i = 0; i < 8; i++)
#pragma unroll
        for (int j = 0; j < 4; j++) o[i][j] = 0.0f;

    for (int kb = 0; kb <= qb_local; kb++) {
        const int tok0 = seq_start + kb * 64;
        // ---- load K hi/lo + Vt hi/lo (64KB, 16 chunks/thread) ----
#pragma unroll
        for (int t = 0; t < 8; t++) {
            int id = tid + t * 256;
            int buf = id >> 10;
            int w = id & 1023;
            int half_ = w >> 9;
            int w2 = w & 511;
            int trow = w2 >> 3, cch = w2 & 7;
            const __half* src = (buf ? Klo : Khi) +
                (size_t)(tok0 + trow) * (KVH * HD) + kh * HD + half_ * 64 + cch * 8;
            cp_async16(sbm + (buf ? ATT_KLO : ATT_KHI) + half_ * 8192 + swoff(trow, cch), src);
        }
#pragma unroll
        for (int t = 0; t < 8; t++) {
            int id = tid + t * 256;
            int buf = id >> 10;
            int w = id & 1023;
            int drow = w >> 3, cch = w & 7;
            int half_ = drow >> 6, rl = drow & 63;
            const __half* src = (buf ? Vtlo : Vthi) +
                ((size_t)kh * HD + drow) * T_TOK + tok0 + cch * 8;
            cp_async16(sbm + (buf ? ATT_VLO : ATT_VHI) + half_ * 8192 + swoff(rl, cch), src);
        }
        cp_commit();
        cp_wait<0>();
        __syncthreads();

        // ---- QK^T 2-pass: q16*(Khi + Klo) ----
        float sacc[4][4];
#pragma unroll
        for (int i = 0; i < 4; i++)
#pragma unroll
            for (int j = 0; j < 4; j++) sacc[i][j] = 0.0f;

#pragma unroll
        for (int half_ = 0; half_ < 2; half_++) {
#pragma unroll
            for (int s4 = 0; s4 < 4; s4++) {
                uint32_t aq[4];
                ldsm4(aq, sbm + ATT_Q + half_ * 8192 + swoff(a_row, (s4 << 1) + a_csel));
                uint32_t bh[2][4], bl[2][4];
#pragma unroll
                for (int jb = 0; jb < 2; jb++) {
                    uint32_t offb = half_ * 8192 +
                                    swoff(b_row + jb * 16, (s4 << 1) + b_csel);
                    ldsm4(bh[jb], sbm + ATT_KHI + offb);
                    ldsm4(bl[jb], sbm + ATT_KLO + offb);
                }
#pragma unroll
                for (int nj = 0; nj < 4; nj++) {
                    mma16816(sacc[nj], aq, &bh[nj >> 1][(nj & 1) * 2]);
                    mma16816(sacc[nj], aq, &bl[nj >> 1][(nj & 1) * 2]);
                }
            }
        }

        // ---- write S with scale + causal mask ----
        const bool diag = (kb == qb_local);
#pragma unroll
        for (int nj = 0; nj < 4; nj++) {
            int mloc = warp_m * 16 + qrow;
            int cloc = warp_n * 32 + nj * 8 + qcol;
            float v0 = sacc[nj][0] * SCALE;
            float v1 = sacc[nj][1] * SCALE;
            float v2 = sacc[nj][2] * SCALE;
            float v3 = sacc[nj][3] * SCALE;
            if (diag) {
                if (cloc     > mloc)     v0 = -1e30f;
                if (cloc + 1 > mloc)     v1 = -1e30f;
                if (cloc     > mloc + 8) v2 = -1e30f;
                if (cloc + 1 > mloc + 8) v3 = -1e30f;
            }
            Ss[mloc * 68 + cloc]           = v0;
            Ss[mloc * 68 + cloc + 1]       = v1;
            Ss[(mloc + 8) * 68 + cloc]     = v2;
            Ss[(mloc + 8) * 68 + cloc + 1] = v3;
        }
        __syncthreads();

        // ---- online softmax, P -> fp16 swizzled ----
        {
            float lmax = -INFINITY;
            int base = srow * 68 + sq * 16;
#pragma unroll
            for (int jj = 0; jj < 16; jj++)
                lmax = fmaxf(lmax, Ss[base + jj]);
            lmax = fmaxf(lmax, __shfl_xor_sync(0xffffffffu, lmax, 1));
            lmax = fmaxf(lmax, __shfl_xor_sync(0xffffffffu, lmax, 2));
            float m_new = fmaxf(m_run, lmax);
            float alpha = __expf(m_run - m_new);
            float lsum = 0.0f;
#pragma unroll
            for (int jj = 0; jj < 16; jj += 2) {
                float p0 = __expf(Ss[base + jj] - m_new);
                float p1 = __expf(Ss[base + jj + 1] - m_new);
                lsum += p0 + p1;
                int col = sq * 16 + jj;
                uint32_t byte = (uint32_t)(srow * 128) +
                    ((((col >> 3)) ^ (srow & 7)) << 4) + (col & 7) * 2;
                *(__half2*)(smc + ATT_PS + byte) = __floats2half2_rn(p0, p1);
            }
            lsum += __shfl_xor_sync(0xffffffffu, lsum, 1);
            lsum += __shfl_xor_sync(0xffffffffu, lsum, 2);
            l_run = l_run * alpha + lsum;
            m_run = m_new;
            if ((tid & 3) == 0) { alphas[srow] = alpha; lrow[srow] = l_run; }
        }
        __syncthreads();

        // ---- PV: o = o*alpha + P @ (Vhi + Vlo) ----
        {
            float a0 = alphas[warp_m * 16 + qrow];
            float a1 = alphas[warp_m * 16 + qrow + 8];
#pragma unroll
            for (int nj = 0; nj < 8; nj++) {
                o[nj][0] *= a0; o[nj][1] *= a0;
                o[nj][2] *= a1; o[nj][3] *= a1;
            }
#pragma unroll
            for (int s4 = 0; s4 < 4; s4++) {
                uint32_t ap[4];
                ldsm4(ap, sbm + ATT_PS + swoff(a_row, (s4 << 1) + a_csel));
                uint32_t vh[4][4], vl[4][4];
#pragma unroll
                for (int nb = 0; nb < 4; nb++) {
                    uint32_t offv = warp_n * 8192 +
                        swoff(pb_row + nb * 16, (s4 << 1) + b_csel);
                    ldsm4(vh[nb], sbm + ATT_VHI + offv);
                    ldsm4(vl[nb], sbm + ATT_VLO + offv);
                }
#pragma unroll
                for (int nj = 0; nj < 8; nj++) {
                    mma16816(o[nj], ap, &vh[nj >> 1][(nj & 1) * 2]);
                    mma16816(o[nj], ap, &vl[nj >> 1][(nj & 1) * 2]);
                }
            }
        }
        __syncthreads();   // protect K/V/PS before next iteration's loads
    }

    float inv0 = 1.0f / lrow[warp_m * 16 + qrow];
    float inv1 = 1.0f / lrow[warp_m * 16 + qrow + 8];
#pragma unroll
    for (int nj = 0; nj < 8; nj++) {
        int m = q_start + warp_m * 16 + qrow;
        int col = h * HD + warp_n * 64 + nj * 8 + qcol;
        *(__half2*)(oh + (size_t)m * DM + col) =
            __floats2half2_rn(o[nj][0] * inv0, o[nj][1] * inv0);
        *(__half2*)(oh + (size_t)(m + 8) * DM + col) =
            __floats2half2_rn(o[nj][2] * inv1, o[nj][3] * inv1);
    }
}

// ============================================================================
// launch
// ============================================================================
extern "C" void kernel_launch(void* const* d_in, const int* in_sizes, int n_in,
                              void* d_out, int out_size)
{
    const float* hs    = (const float*)d_in[0];
    const float* w_qkv = (const float*)d_in[1];
    const float* w_o   = (const float*)d_in[2];
    const float* cs    = (const float*)d_in[3];
    const float* sn    = (const float*)d_in[4];
    (void)in_sizes; (void)n_in;

    __half *ah, *bq, *bo, *qh, *khi, *klo, *vthi, *vtlo;
    cudaGetSymbolAddress((void**)&ah, g_ah);
    cudaGetSymbolAddress((void**)&bq, g_bq);
    cudaGetSymbolAddress((void**)&bo, g_bo);
    cudaGetSymbolAddress((void**)&qh, g_qh);
    cudaGetSymbolAddress((void**)&khi, g_khi);
    cudaGetSymbolAddress((void**)&klo, g_klo);
    cudaGetSymbolAddress((void**)&vthi, g_vthi);
    cudaGetSymbolAddress((void**)&vtlo, g_vtlo);

    static cudaStream_t s1 = nullptr, s2 = nullptr;
    static cudaEvent_t eFork = nullptr, eWqkv = nullptr, eWo = nullptr;
    static int init_done = 0;
    if (!init_done) {
        cudaFuncSetAttribute(attn_kernel, cudaFuncAttributeMaxDynamicSharedMemorySize,
                             ATT_SMEM);
        cudaFuncSetAttribute(gemm1p_kernel<0>,
                             cudaFuncAttributeMaxDynamicSharedMemorySize, GEMM1P_SMEM);
        cudaFuncSetAttribute(gemm1p_kernel<1>,
                             cudaFuncAttributeMaxDynamicSharedMemorySize, GEMM1P_SMEM);
        cudaStreamCreateWithFlags(&s1, cudaStreamNonBlocking);
        cudaStreamCreateWithFlags(&s2, cudaStreamNonBlocking);
        cudaEventCreateWithFlags(&eFork, cudaEventDisableTiming);
        cudaEventCreateWithFlags(&eWqkv, cudaEventDisableTiming);
        cudaEventCreateWithFlags(&eWo, cudaEventDisableTiming);
        init_done = 1;
    }

    cudaEventRecord(eFork, 0);
    cudaStreamWaitEvent(s1, eFork, 0);
    cudaStreamWaitEvent(s2, eFork, 0);

    cvt_half_kernel<<<(QKV_N * DM / 8) / 256, 256, 0, s1>>>(w_qkv, bq, QKV_N * DM / 8);
    cudaEventRecord(eWqkv, s1);

    cvt_half_kernel<<<(DM * DM / 8) / 256, 256, 0, s2>>>(w_o, bo, DM * DM / 8);
    cudaEventRecord(eWo, s2);

    cvt_half_kernel<<<(T_TOK * DM / 8) / 256, 256>>>(hs, ah, T_TOK * DM / 8);
    cudaStreamWaitEvent(0, eWqkv, 0);

    // QKV projection (1-pass) with fused clip+RoPE+split / V-transpose epilogue
    gemm1p_kernel<1><<<dim3(QKV_N / 128, T_TOK / 128), 256, GEMM1P_SMEM>>>(
        ah, bq, nullptr, QKV_N, cs, sn, qh, khi, klo, vthi, vtlo);

    // tensor-core flash attention (occ 2) -> fp16 O into g_ah
    attn_kernel<<<dim3(32, NH), 256, ATT_SMEM>>>(qh, khi, klo, vthi, vtlo, ah);

    // output projection (1-pass)
    cudaStreamWaitEvent(0, eWo, 0);
    gemm1p_kernel<0><<<dim3(DM / 128, T_TOK / 128), 256, GEMM1P_SMEM>>>(
        ah, bo, (float*)d_out, DM, nullptr, nullptr,
        nullptr, nullptr, nullptr, nullptr, nullptr);
}